// round 1
// baseline (speedup 1.0000x reference)
#include <cuda_runtime.h>
#include <math.h>

#define OBS 8
#define PRED 4
#define NAG 256
#define FIN 2
#define FOUT 2
#define H 128
#define NH 8
#define DH 16
#define FFD 2048
#define NL 6
#define NNODE (OBS*NAG)        /* 2048 */
#define SEQ NAG                /* 256  */
#define BB H                   /* 128  */
#define NTOK (SEQ*BB)          /* 32768 */

// ---------------- scratch (device globals; no allocation) ----------------
static __device__ float g_ADJ[NNODE*NNODE];
static __device__ float g_AGG[NNODE*NNODE];
static __device__ float g_ENC[NNODE*H];
static __device__ float g_MLINT[H*NNODE];
static __device__ float g_LSLINT[H*NNODE];
static __device__ float g_MU[NNODE*H];
static __device__ float g_LSR[NNODE*H];
static __device__ float g_Z[NNODE*H];
static __device__ float g_OUTB[NNODE*H];
static __device__ float g_X[NTOK*H];
static __device__ float g_TMP[NTOK*H];
static __device__ float g_O[NTOK*H];
static __device__ float g_QKV[NTOK*3*H];
static __device__ float g_FFH[(size_t)NTOK*FFD];
static __device__ float g_COL[NNODE];
static __device__ float g_SELF[NNODE];
static __device__ float g_DIS[NNODE];
static __device__ float g_mn_acc, g_mx_acc;
static __device__ double g_kld, g_struct, g_traj;

// ---------------- helpers ----------------
__device__ __forceinline__ void atomicMinF(float* a, float v) {
    int* ai = (int*)a;
    int old = *ai;
    while (__int_as_float(old) > v) {
        int assumed = old;
        old = atomicCAS(ai, assumed, __float_as_int(v));
        if (old == assumed) break;
    }
}
__device__ __forceinline__ void atomicMaxF(float* a, float v) {
    int* ai = (int*)a;
    int old = *ai;
    while (__int_as_float(old) < v) {
        int assumed = old;
        old = atomicCAS(ai, assumed, __float_as_int(v));
        if (old == assumed) break;
    }
}

template<int NWARPS>
__device__ __forceinline__ float block_sum(float v) {
    __shared__ float w[NWARPS];
    int tid = threadIdx.x + threadIdx.y * blockDim.x;
    int lane = tid & 31, wid = tid >> 5;
    #pragma unroll
    for (int o = 16; o > 0; o >>= 1) v += __shfl_down_sync(0xffffffffu, v, o);
    if (lane == 0) w[wid] = v;
    __syncthreads();
    float r = 0.f;
    #pragma unroll
    for (int i = 0; i < NWARPS; i++) r += w[i];
    __syncthreads();
    return r;
}

// ---------------- init ----------------
__global__ void k_init() {
    int i = blockIdx.x * 256 + threadIdx.x;
    if (i < NNODE) g_COL[i] = 0.f;
    if (i == 0) {
        g_mn_acc = __int_as_float(0x7f800000);
        g_mx_acc = __int_as_float(0xff800000);
        g_kld = 0.0; g_struct = 0.0; g_traj = 0.0;
    }
}

// ---------------- adjacency prep ----------------
__global__ void k_minmax(const float* __restrict__ adj) {
    const int n = OBS * NAG * NAG;
    float mn = __int_as_float(0x7f800000), mx = -mn;
    for (int i = blockIdx.x * blockDim.x + threadIdx.x; i < n; i += gridDim.x * blockDim.x) {
        float v = adj[i];
        mn = fminf(mn, v);
        mx = fmaxf(mx, v);
    }
    #pragma unroll
    for (int o = 16; o > 0; o >>= 1) {
        mn = fminf(mn, __shfl_down_sync(0xffffffffu, mn, o));
        mx = fmaxf(mx, __shfl_down_sync(0xffffffffu, mx, o));
    }
    __shared__ float smn[8], smx[8];
    int lane = threadIdx.x & 31, wid = threadIdx.x >> 5;
    if (lane == 0) { smn[wid] = mn; smx[wid] = mx; }
    __syncthreads();
    if (threadIdx.x == 0) {
        for (int w = 1; w < 8; w++) { mn = fminf(mn, smn[w]); mx = fmaxf(mx, smx[w]); }
        atomicMinF(&g_mn_acc, mn);
        atomicMaxF(&g_mx_acc, mx);
    }
}

// ADJ[i,j] = (A[i,j]-mn)/(mx-mn), A block-diagonal from adj_in; also self-loop mask
__global__ void k_build(const float* __restrict__ adj) {
    float mn = fminf(g_mn_acc, 0.f);
    float mx = fmaxf(g_mx_acc, 0.f);
    float inv = 1.f / (mx - mn);
    int i = blockIdx.y;
    int j = blockIdx.x * 256 + threadIdx.x;
    int ti = i >> 8, tj = j >> 8;
    float a = (ti == tj) ? adj[(ti << 16) + ((i & 255) << 8) + (j & 255)] : 0.f;
    float v = (a - mn) * inv;
    g_ADJ[i * NNODE + j] = v;
    if (i == j) g_SELF[i] = (v == 0.f) ? 1.f : 0.f;
}

__global__ void k_colsum() {
    int j = blockIdx.x * 128 + threadIdx.x;
    int i0 = blockIdx.y * 128;
    float s = 0.f;
    for (int r = 0; r < 128; r++) s += g_ADJ[(size_t)(i0 + r) * NNODE + j];
    atomicAdd(&g_COL[j], s);
}

__global__ void k_dis() {
    int j = blockIdx.x * 256 + threadIdx.x;
    if (j < NNODE) {
        float deg = g_COL[j] + g_SELF[j];
        g_DIS[j] = (deg > 0.f) ? (1.f / sqrtf(deg)) : 0.f;
    }
}

// agg[i,j] = dis[j] * A_sl[j,i] * dis[i]
__global__ void k_agg() {
    __shared__ float s[32][33];
    int i0 = blockIdx.y * 32, j0 = blockIdx.x * 32;
    int tx = threadIdx.x, ty = threadIdx.y;
    s[ty][tx] = g_ADJ[(size_t)(j0 + ty) * NNODE + (i0 + tx)];
    __syncthreads();
    int i = i0 + ty, j = j0 + tx;
    float v = s[tx][ty]; // = ADJ[j][i]
    if (i == j) v += g_SELF[i];
    g_AGG[(size_t)i * NNODE + j] = g_DIS[j] * v * g_DIS[i];
}

// ---------------- encoder ----------------
__global__ void k_enc(const float* __restrict__ traj,
                      const float* __restrict__ w1, const float* __restrict__ b1,
                      const float* __restrict__ w2, const float* __restrict__ b2) {
    int n = blockIdx.x, j = threadIdx.x;
    __shared__ float h1[128];
    float x0 = traj[n * 2], x1 = traj[n * 2 + 1];
    h1[j] = fmaxf(w1[j * 2] * x0 + w1[j * 2 + 1] * x1 + b1[j], 0.f);
    __syncthreads();
    float a = b2[j];
    #pragma unroll 8
    for (int k = 0; k < 128; k++) a += w2[j * 128 + k] * h1[k];
    g_ENC[n * 128 + j] = a;
}

// ---------------- generic SGEMM: C[M,N] = A[M,K] * B[N,K]^T + bias ----------------
// M % 64 == 0, N % 64 == 0, K % 16 == 0 required.
__global__ __launch_bounds__(256) void k_gemm(
    const float* __restrict__ A, const float* __restrict__ B,
    const float* __restrict__ bias, float* __restrict__ C,
    int M, int N, int K, int relu, int storeT)
{
    __shared__ float As[16][64];
    __shared__ float Bs[16][64];
    int bm = blockIdx.y * 64, bn = blockIdx.x * 64;
    int tid = threadIdx.x;
    int tx = tid & 15, ty = tid >> 4;
    int lr = tid >> 2, lc4 = (tid & 3) * 4;
    float acc[4][4] = {};
    for (int k0 = 0; k0 < K; k0 += 16) {
        float4 a4 = *(const float4*)(A + (size_t)(bm + lr) * K + k0 + lc4);
        float4 b4 = *(const float4*)(B + (size_t)(bn + lr) * K + k0 + lc4);
        As[lc4 + 0][lr] = a4.x; As[lc4 + 1][lr] = a4.y; As[lc4 + 2][lr] = a4.z; As[lc4 + 3][lr] = a4.w;
        Bs[lc4 + 0][lr] = b4.x; Bs[lc4 + 1][lr] = b4.y; Bs[lc4 + 2][lr] = b4.z; Bs[lc4 + 3][lr] = b4.w;
        __syncthreads();
        #pragma unroll
        for (int k = 0; k < 16; k++) {
            float ra[4], rb[4];
            #pragma unroll
            for (int i = 0; i < 4; i++) ra[i] = As[k][ty * 4 + i];
            #pragma unroll
            for (int j = 0; j < 4; j++) rb[j] = Bs[k][tx * 4 + j];
            #pragma unroll
            for (int i = 0; i < 4; i++)
                #pragma unroll
                for (int j = 0; j < 4; j++)
                    acc[i][j] += ra[i] * rb[j];
        }
        __syncthreads();
    }
    #pragma unroll
    for (int i = 0; i < 4; i++) {
        int row = bm + ty * 4 + i;
        #pragma unroll
        for (int j = 0; j < 4; j++) {
            int col = bn + tx * 4 + j;
            float v = acc[i][j];
            if (bias) v += bias[col];
            if (relu) v = fmaxf(v, 0.f);
            if (storeT) C[(size_t)col * M + row] = v;
            else        C[(size_t)row * N + col] = v;
        }
    }
}

// ---------------- reparameterization + KLD ----------------
__global__ void k_z(const float* __restrict__ eps, const int* __restrict__ iftrain) {
    int idx = blockIdx.x * 256 + threadIdx.x;   // 262144 total
    float m = g_MU[idx];
    float ls = fminf(g_LSR[idx], 10.f);
    float zz = (*iftrain > 0) ? (m + eps[idx] * expf(ls)) : m;
    g_Z[idx] = zz;
    float term = 1.f + 2.f * ls - m * m - expf(2.f * ls);
    float bs = block_sum<8>(term);
    if (threadIdx.x == 0) atomicAdd(&g_kld, (double)bs);
}

// ---------------- struct loss: fused Z Z^T + BCE-ish reduce ----------------
__global__ __launch_bounds__(1024) void k_struct() {
    __shared__ float Zi[32][129];
    __shared__ float Zj[32][129];
    int i0 = blockIdx.y * 32, j0 = blockIdx.x * 32;
    int tid = threadIdx.y * 32 + threadIdx.x;
    for (int idx = tid; idx < 32 * 128; idx += 1024) {
        int r = idx >> 7, c = idx & 127;
        Zi[r][c] = g_Z[(size_t)(i0 + r) * H + c];
        Zj[r][c] = g_Z[(size_t)(j0 + r) * H + c];
    }
    __syncthreads();
    int ty = threadIdx.y, tx = threadIdx.x;
    float acc = 0.f;
    #pragma unroll 8
    for (int k = 0; k < 128; k++) acc += Zi[ty][k] * Zj[tx][k];
    int i = i0 + ty, j = j0 + tx;
    float adj = g_ADJ[(size_t)i * NNODE + j];
    float contrib = fmaxf(acc, 0.f) - acc * adj + log1pf(expf(-fabsf(acc)));
    float bs = block_sum<32>(contrib);
    if (tid == 0) atomicAdd(&g_struct, (double)bs);
}

// ---------------- build transformer input x ----------------
// X[(a*128+h)*128 + j] = sum_t OUTB[(t*256+a)*128+h] * pro3_w[j*8+t] + pro3_b[j]
__global__ void k_xbuild(const float* __restrict__ w3, const float* __restrict__ b3) {
    int idx = blockIdx.x * 256 + threadIdx.x;   // 4194304 total
    int j = idx & 127;
    int tok = idx >> 7;
    int a = tok >> 7, h = tok & 127;
    float acc = b3[j];
    #pragma unroll
    for (int t = 0; t < OBS; t++)
        acc += g_OUTB[(size_t)((t << 8) + a) * H + h] * w3[j * OBS + t];
    g_X[idx] = acc;
}

// ---------------- attention (per batch,head block; flash-style) ----------------
__global__ __launch_bounds__(256) void k_attn() {
    __shared__ float Ks[256][16];
    __shared__ float Vs[256][16];
    int bh = blockIdx.x;
    int b = bh >> 3, h = bh & 7;
    int t = threadIdx.x;
    const float* kptr = g_QKV + ((size_t)t * BB + b) * (3 * H) + H + h * DH;
    const float* vptr = kptr + H;
    #pragma unroll
    for (int d4 = 0; d4 < 4; d4++) {
        float4 kv = *(const float4*)(kptr + d4 * 4);
        Ks[t][d4 * 4 + 0] = kv.x; Ks[t][d4 * 4 + 1] = kv.y;
        Ks[t][d4 * 4 + 2] = kv.z; Ks[t][d4 * 4 + 3] = kv.w;
        float4 vv = *(const float4*)(vptr + d4 * 4);
        Vs[t][d4 * 4 + 0] = vv.x; Vs[t][d4 * 4 + 1] = vv.y;
        Vs[t][d4 * 4 + 2] = vv.z; Vs[t][d4 * 4 + 3] = vv.w;
    }
    __syncthreads();
    int s = threadIdx.x;
    float q[16];
    const float* qptr = g_QKV + ((size_t)s * BB + b) * (3 * H) + h * DH;
    #pragma unroll
    for (int d = 0; d < 16; d++) q[d] = qptr[d];
    float m = __int_as_float(0xff800000), l = 0.f;
    float o[16] = {};
    for (int tt = 0; tt < 256; tt++) {
        float sc = 0.f;
        #pragma unroll
        for (int d = 0; d < 16; d++) sc += q[d] * Ks[tt][d];
        sc *= 0.25f;   // 1/sqrt(16)
        float mn = fmaxf(m, sc);
        float corr = __expf(m - mn);
        float p = __expf(sc - mn);
        l = l * corr + p;
        #pragma unroll
        for (int d = 0; d < 16; d++) o[d] = o[d] * corr + p * Vs[tt][d];
        m = mn;
    }
    float invl = 1.f / l;
    float* op = g_O + ((size_t)s * BB + b) * H + h * DH;
    #pragma unroll
    for (int d = 0; d < 16; d++) op[d] = o[d] * invl;
}

// ---------------- residual add + LayerNorm (per token) ----------------
__global__ void k_addln(const float* __restrict__ g, const float* __restrict__ bet) {
    int t = blockIdx.x, j = threadIdx.x;
    float v = g_X[(size_t)t * H + j] + g_TMP[(size_t)t * H + j];
    float mean = block_sum<4>(v) * (1.f / 128.f);
    float d = v - mean;
    float var = block_sum<4>(d * d) * (1.f / 128.f);
    g_X[(size_t)t * H + j] = d * (1.f / sqrtf(var + 1e-5f)) * g[j] + bet[j];
}

// ---------------- final projection + traj output + traj loss ----------------
__global__ void k_traj(const float* __restrict__ w4, const float* __restrict__ b4,
                       const float* __restrict__ w5, const float* __restrict__ b5,
                       const float* __restrict__ traj_in, float* __restrict__ out) {
    int tt = blockIdx.x >> 8;      // 0..3  (pred step)
    int a  = blockIdx.x & 255;     // agent
    int b  = threadIdx.x;          // 0..127
    int o = tt + (OBS - PRED);     // 4..7
    const float* xr = g_X + ((size_t)a * 128 + b) * 128;
    float acc = b4[o];
    #pragma unroll 8
    for (int j = 0; j < 128; j++) acc += xr[j] * w4[o * 128 + j];
    float s0 = block_sum<4>(acc * w5[b]);
    float s1 = block_sum<4>(acc * w5[128 + b]);
    if (b == 0) {
        float t0 = s0 + b5[0], t1 = s1 + b5[1];
        float y0 = traj_in[(OBS + tt) * (NAG * 2) + a * 2 + 0];
        float y1 = traj_in[(OBS + tt) * (NAG * 2) + a * 2 + 1];
        out[(tt * 256 + a) * 2 + 0] = t0;
        out[(tt * 256 + a) * 2 + 1] = t1;
        float d0 = t0 - y0, d1 = t1 - y1;
        atomicAdd(&g_traj, (double)sqrtf(d0 * d0 + d1 * d1));
    }
}

__global__ void k_final(float* __restrict__ out) {
    double kld = -0.5 * (g_kld / 2048.0);
    double st = g_struct / (2048.0 * 2048.0);
    double tl = g_traj / 256.0;
    out[PRED * NAG * FOUT] = (float)(tl + kld + st);
}

// ---------------- launch ----------------
extern "C" void kernel_launch(void* const* d_in, const int* in_sizes, int n_in,
                              void* d_out, int out_size) {
    const float* traj_in = (const float*)d_in[0];
    const float* adj_in  = (const float*)d_in[1];
    const float* eps     = (const float*)d_in[2];
    const float* pro1_w  = (const float*)d_in[3];
    const float* pro1_b  = (const float*)d_in[4];
    const float* pro2_w  = (const float*)d_in[5];
    const float* pro2_b  = (const float*)d_in[6];
    const float* mu_w    = (const float*)d_in[7];
    const float* mu_b    = (const float*)d_in[8];
    const float* ls_w    = (const float*)d_in[9];
    const float* ls_b    = (const float*)d_in[10];
    const float* gdl_w   = (const float*)d_in[11];
    const float* gdl_b   = (const float*)d_in[12];
    const float* pro3_w  = (const float*)d_in[13];
    const float* pro3_b  = (const float*)d_in[14];
    const float* pro4_w  = (const float*)d_in[15];
    const float* pro4_b  = (const float*)d_in[16];
    const float* pro5_w  = (const float*)d_in[17];
    const float* pro5_b  = (const float*)d_in[18];
    const float* qkv_w   = (const float*)d_in[19];
    const float* qkv_b   = (const float*)d_in[20];
    const float* out_w   = (const float*)d_in[21];
    const float* out_b   = (const float*)d_in[22];
    const float* ff1_w   = (const float*)d_in[23];
    const float* ff1_b   = (const float*)d_in[24];
    const float* ff2_w   = (const float*)d_in[25];
    const float* ff2_b   = (const float*)d_in[26];
    const float* ln1_g   = (const float*)d_in[27];
    const float* ln1_b   = (const float*)d_in[28];
    const float* ln2_g   = (const float*)d_in[29];
    const float* ln2_b   = (const float*)d_in[30];
    const int*   iftrain = (const int*)d_in[31];
    float* out = (float*)d_out;

    float *pENC, *pMLINT, *pLSLINT, *pAGG, *pMU, *pLSR, *pZ, *pOUTB, *pX, *pTMP, *pO, *pQKV, *pFFH;
    cudaGetSymbolAddress((void**)&pENC,    g_ENC);
    cudaGetSymbolAddress((void**)&pMLINT,  g_MLINT);
    cudaGetSymbolAddress((void**)&pLSLINT, g_LSLINT);
    cudaGetSymbolAddress((void**)&pAGG,    g_AGG);
    cudaGetSymbolAddress((void**)&pMU,     g_MU);
    cudaGetSymbolAddress((void**)&pLSR,    g_LSR);
    cudaGetSymbolAddress((void**)&pZ,      g_Z);
    cudaGetSymbolAddress((void**)&pOUTB,   g_OUTB);
    cudaGetSymbolAddress((void**)&pX,      g_X);
    cudaGetSymbolAddress((void**)&pTMP,    g_TMP);
    cudaGetSymbolAddress((void**)&pO,      g_O);
    cudaGetSymbolAddress((void**)&pQKV,    g_QKV);
    cudaGetSymbolAddress((void**)&pFFH,    g_FFH);

    // ---- graph-VAE front end ----
    k_init<<<8, 256>>>();
    k_minmax<<<512, 256>>>(adj_in);
    k_build<<<dim3(8, NNODE), 256>>>(adj_in);
    k_colsum<<<dim3(16, 16), 128>>>();
    k_dis<<<8, 256>>>();
    k_agg<<<dim3(64, 64), dim3(32, 32)>>>();
    k_enc<<<NNODE, 128>>>(traj_in, pro1_w, pro1_b, pro2_w, pro2_b);

    // mu_lin^T, ls_lin^T (store transposed so AGG gemm sees B as (N,K))
    k_gemm<<<dim3(2, 32), 256>>>(pENC, mu_w, mu_b, pMLINT, NNODE, H, H, 0, 1);
    k_gemm<<<dim3(2, 32), 256>>>(pENC, ls_w, ls_b, pLSLINT, NNODE, H, H, 0, 1);
    // MU = AGG @ mu_lin ; LSR = AGG @ ls_lin
    k_gemm<<<dim3(2, 32), 256>>>(pAGG, pMLINT, nullptr, pMU, NNODE, H, NNODE, 0, 0);
    k_gemm<<<dim3(2, 32), 256>>>(pAGG, pLSLINT, nullptr, pLSR, NNODE, H, NNODE, 0, 0);
    k_z<<<1024, 256>>>(eps, iftrain);
    k_struct<<<dim3(64, 64), dim3(32, 32)>>>();
    k_gemm<<<dim3(2, 32), 256>>>(pZ, gdl_w, gdl_b, pOUTB, NNODE, H, H, 0, 0);
    k_xbuild<<<16384, 256>>>(pro3_w, pro3_b);

    // ---- transformer ----
    for (int l = 0; l < NL; l++) {
        k_gemm<<<dim3(6, 512), 256>>>(pX, qkv_w + (size_t)l * 3 * H * H, qkv_b + (size_t)l * 3 * H,
                                      pQKV, NTOK, 3 * H, H, 0, 0);
        k_attn<<<BB * NH, 256>>>();
        k_gemm<<<dim3(2, 512), 256>>>(pO, out_w + (size_t)l * H * H, out_b + (size_t)l * H,
                                      pTMP, NTOK, H, H, 0, 0);
        k_addln<<<NTOK, 128>>>(ln1_g + l * H, ln1_b + l * H);
        k_gemm<<<dim3(32, 512), 256>>>(pX, ff1_w + (size_t)l * FFD * H, ff1_b + (size_t)l * FFD,
                                       pFFH, NTOK, FFD, H, 1, 0);
        k_gemm<<<dim3(2, 512), 256>>>(pFFH, ff2_w + (size_t)l * H * FFD, ff2_b + (size_t)l * H,
                                      pTMP, NTOK, H, FFD, 0, 0);
        k_addln<<<NTOK, 128>>>(ln2_g + l * H, ln2_b + l * H);
    }

    // ---- output + loss ----
    k_traj<<<PRED * NAG, 128>>>(pro4_w, pro4_b, pro5_w, pro5_b, traj_in, out);
    k_final<<<1, 1>>>(out);
}

// round 2
// speedup vs baseline: 2.3311x; 2.3311x over previous
#include <cuda_runtime.h>
#include <math.h>

#define OBS 8
#define PRED 4
#define NAG 256
#define FIN 2
#define FOUT 2
#define H 128
#define NH 8
#define DH 16
#define FFD 2048
#define NL 6
#define NNODE (OBS*NAG)        /* 2048 */
#define SEQ NAG                /* 256  */
#define BB H                   /* 128  */
#define NTOK (SEQ*BB)          /* 32768 */

// ---------------- scratch (device globals; no allocation) ----------------
static __device__ float g_ADJ[NNODE*NNODE];
static __device__ float g_AGG[NNODE*NNODE];
static __device__ float g_ENC[NNODE*H];
static __device__ float g_MLINT[H*NNODE];
static __device__ float g_LSLINT[H*NNODE];
static __device__ float g_MU[NNODE*H];
static __device__ float g_LSR[NNODE*H];
static __device__ float g_Z[NNODE*H];
static __device__ float g_OUTB[NNODE*H];
static __device__ float g_X[NTOK*H];
static __device__ float g_TMP[NTOK*H];
static __device__ float g_O[NTOK*H];
static __device__ float g_QKV[NTOK*3*H];
static __device__ float g_FFH[(size_t)NTOK*FFD];
static __device__ float g_COL[NNODE];
static __device__ float g_SELF[NNODE];
static __device__ float g_DIS[NNODE];
static __device__ float g_mn_acc, g_mx_acc;
static __device__ double g_kld, g_struct, g_traj;

// ---------------- helpers ----------------
__device__ __forceinline__ void atomicMinF(float* a, float v) {
    int* ai = (int*)a;
    int old = *ai;
    while (__int_as_float(old) > v) {
        int assumed = old;
        old = atomicCAS(ai, assumed, __float_as_int(v));
        if (old == assumed) break;
    }
}
__device__ __forceinline__ void atomicMaxF(float* a, float v) {
    int* ai = (int*)a;
    int old = *ai;
    while (__int_as_float(old) < v) {
        int assumed = old;
        old = atomicCAS(ai, assumed, __float_as_int(v));
        if (old == assumed) break;
    }
}

template<int NWARPS>
__device__ __forceinline__ float block_sum(float v) {
    __shared__ float w[NWARPS];
    int tid = threadIdx.x + threadIdx.y * blockDim.x;
    int lane = tid & 31, wid = tid >> 5;
    #pragma unroll
    for (int o = 16; o > 0; o >>= 1) v += __shfl_down_sync(0xffffffffu, v, o);
    if (lane == 0) w[wid] = v;
    __syncthreads();
    float r = 0.f;
    #pragma unroll
    for (int i = 0; i < NWARPS; i++) r += w[i];
    __syncthreads();
    return r;
}

__device__ __forceinline__ unsigned f2tf(float f) {
    unsigned u;
    asm("cvt.rna.tf32.f32 %0, %1;" : "=r"(u) : "f"(f));
    return u;
}

__device__ __forceinline__ void mma_tf32(float* c, const unsigned* a, unsigned b0, unsigned b1) {
    asm volatile(
        "mma.sync.aligned.m16n8k8.row.col.f32.tf32.tf32.f32 "
        "{%0,%1,%2,%3}, {%4,%5,%6,%7}, {%8,%9}, {%0,%1,%2,%3};"
        : "+f"(c[0]), "+f"(c[1]), "+f"(c[2]), "+f"(c[3])
        : "r"(a[0]), "r"(a[1]), "r"(a[2]), "r"(a[3]), "r"(b0), "r"(b1));
}

// ---------------- init ----------------
__global__ void k_init() {
    int i = blockIdx.x * 256 + threadIdx.x;
    if (i < NNODE) g_COL[i] = 0.f;
    if (i == 0) {
        g_mn_acc = __int_as_float(0x7f800000);
        g_mx_acc = __int_as_float(0xff800000);
        g_kld = 0.0; g_struct = 0.0; g_traj = 0.0;
    }
}

// ---------------- adjacency prep ----------------
__global__ void k_minmax(const float* __restrict__ adj) {
    const int n = OBS * NAG * NAG;
    float mn = __int_as_float(0x7f800000), mx = -mn;
    for (int i = blockIdx.x * blockDim.x + threadIdx.x; i < n; i += gridDim.x * blockDim.x) {
        float v = adj[i];
        mn = fminf(mn, v);
        mx = fmaxf(mx, v);
    }
    #pragma unroll
    for (int o = 16; o > 0; o >>= 1) {
        mn = fminf(mn, __shfl_down_sync(0xffffffffu, mn, o));
        mx = fmaxf(mx, __shfl_down_sync(0xffffffffu, mx, o));
    }
    __shared__ float smn[8], smx[8];
    int lane = threadIdx.x & 31, wid = threadIdx.x >> 5;
    if (lane == 0) { smn[wid] = mn; smx[wid] = mx; }
    __syncthreads();
    if (threadIdx.x == 0) {
        for (int w = 1; w < 8; w++) { mn = fminf(mn, smn[w]); mx = fmaxf(mx, smx[w]); }
        atomicMinF(&g_mn_acc, mn);
        atomicMaxF(&g_mx_acc, mx);
    }
}

__global__ void k_build(const float* __restrict__ adj) {
    float mn = fminf(g_mn_acc, 0.f);
    float mx = fmaxf(g_mx_acc, 0.f);
    float inv = 1.f / (mx - mn);
    int i = blockIdx.y;
    int j = blockIdx.x * 256 + threadIdx.x;
    int ti = i >> 8, tj = j >> 8;
    float a = (ti == tj) ? adj[(ti << 16) + ((i & 255) << 8) + (j & 255)] : 0.f;
    float v = (a - mn) * inv;
    g_ADJ[i * NNODE + j] = v;
    if (i == j) g_SELF[i] = (v == 0.f) ? 1.f : 0.f;
}

__global__ void k_colsum() {
    int j = blockIdx.x * 128 + threadIdx.x;
    int i0 = blockIdx.y * 128;
    float s = 0.f;
    for (int r = 0; r < 128; r++) s += g_ADJ[(size_t)(i0 + r) * NNODE + j];
    atomicAdd(&g_COL[j], s);
}

__global__ void k_dis() {
    int j = blockIdx.x * 256 + threadIdx.x;
    if (j < NNODE) {
        float deg = g_COL[j] + g_SELF[j];
        g_DIS[j] = (deg > 0.f) ? (1.f / sqrtf(deg)) : 0.f;
    }
}

__global__ void k_agg() {
    __shared__ float s[32][33];
    int i0 = blockIdx.y * 32, j0 = blockIdx.x * 32;
    int tx = threadIdx.x, ty = threadIdx.y;
    s[ty][tx] = g_ADJ[(size_t)(j0 + ty) * NNODE + (i0 + tx)];
    __syncthreads();
    int i = i0 + ty, j = j0 + tx;
    float v = s[tx][ty];
    if (i == j) v += g_SELF[i];
    g_AGG[(size_t)i * NNODE + j] = g_DIS[j] * v * g_DIS[i];
}

// ---------------- encoder ----------------
__global__ void k_enc(const float* __restrict__ traj,
                      const float* __restrict__ w1, const float* __restrict__ b1,
                      const float* __restrict__ w2, const float* __restrict__ b2) {
    int n = blockIdx.x, j = threadIdx.x;
    __shared__ float h1[128];
    float x0 = traj[n * 2], x1 = traj[n * 2 + 1];
    h1[j] = fmaxf(w1[j * 2] * x0 + w1[j * 2 + 1] * x1 + b1[j], 0.f);
    __syncthreads();
    float a = b2[j];
    #pragma unroll 8
    for (int k = 0; k < 128; k++) a += w2[j * 128 + k] * h1[k];
    g_ENC[n * 128 + j] = a;
}

// ---------------- fp32 SGEMM (used for small/transpose cases) ----------------
__global__ __launch_bounds__(256) void k_gemm(
    const float* __restrict__ A, const float* __restrict__ B,
    const float* __restrict__ bias, float* __restrict__ C,
    int M, int N, int K, int relu, int storeT)
{
    __shared__ float As[16][64];
    __shared__ float Bs[16][64];
    int bm = blockIdx.y * 64, bn = blockIdx.x * 64;
    int tid = threadIdx.x;
    int tx = tid & 15, ty = tid >> 4;
    int lr = tid >> 2, lc4 = (tid & 3) * 4;
    float acc[4][4] = {};
    for (int k0 = 0; k0 < K; k0 += 16) {
        float4 a4 = *(const float4*)(A + (size_t)(bm + lr) * K + k0 + lc4);
        float4 b4 = *(const float4*)(B + (size_t)(bn + lr) * K + k0 + lc4);
        As[lc4 + 0][lr] = a4.x; As[lc4 + 1][lr] = a4.y; As[lc4 + 2][lr] = a4.z; As[lc4 + 3][lr] = a4.w;
        Bs[lc4 + 0][lr] = b4.x; Bs[lc4 + 1][lr] = b4.y; Bs[lc4 + 2][lr] = b4.z; Bs[lc4 + 3][lr] = b4.w;
        __syncthreads();
        #pragma unroll
        for (int k = 0; k < 16; k++) {
            float ra[4], rb[4];
            #pragma unroll
            for (int i = 0; i < 4; i++) ra[i] = As[k][ty * 4 + i];
            #pragma unroll
            for (int j = 0; j < 4; j++) rb[j] = Bs[k][tx * 4 + j];
            #pragma unroll
            for (int i = 0; i < 4; i++)
                #pragma unroll
                for (int j = 0; j < 4; j++)
                    acc[i][j] += ra[i] * rb[j];
        }
        __syncthreads();
    }
    #pragma unroll
    for (int i = 0; i < 4; i++) {
        int row = bm + ty * 4 + i;
        #pragma unroll
        for (int j = 0; j < 4; j++) {
            int col = bn + tx * 4 + j;
            float v = acc[i][j];
            if (bias) v += bias[col];
            if (relu) v = fmaxf(v, 0.f);
            if (storeT) C[(size_t)col * M + row] = v;
            else        C[(size_t)row * N + col] = v;
        }
    }
}

// ---------------- tf32 tensor-core GEMM: C[M,N] = A[M,K] * B[N,K]^T + bias ----
// M%128==0, N%128==0, K%32==0
__global__ __launch_bounds__(256) void k_tgemm(
    const float* __restrict__ A, const float* __restrict__ B,
    const float* __restrict__ bias, float* __restrict__ C,
    int M, int N, int K, int relu)
{
    __shared__ unsigned As[128][36];
    __shared__ unsigned Bs[128][36];
    int bm = blockIdx.y * 128, bn = blockIdx.x * 128;
    int tid = threadIdx.x;
    int warp = tid >> 5, lane = tid & 31;
    int wm = warp & 3, wn = warp >> 2;       // warp tile: rows 32*wm, cols 64*wn
    int g = lane >> 2, tig = lane & 3;

    float acc[2][8][4] = {};

    for (int k0 = 0; k0 < K; k0 += 32) {
        // load A and B tiles (128x32 each), convert to tf32
        #pragma unroll
        for (int i = 0; i < 4; i++) {
            int idx = tid + i * 256;
            int r = idx >> 3, c4 = (idx & 7) * 4;
            float4 a4 = *(const float4*)(A + (size_t)(bm + r) * K + k0 + c4);
            As[r][c4 + 0] = f2tf(a4.x); As[r][c4 + 1] = f2tf(a4.y);
            As[r][c4 + 2] = f2tf(a4.z); As[r][c4 + 3] = f2tf(a4.w);
            float4 b4 = *(const float4*)(B + (size_t)(bn + r) * K + k0 + c4);
            Bs[r][c4 + 0] = f2tf(b4.x); Bs[r][c4 + 1] = f2tf(b4.y);
            Bs[r][c4 + 2] = f2tf(b4.z); Bs[r][c4 + 3] = f2tf(b4.w);
        }
        __syncthreads();
        #pragma unroll
        for (int kk = 0; kk < 32; kk += 8) {
            unsigned a[2][4];
            #pragma unroll
            for (int mt = 0; mt < 2; mt++) {
                int r0 = wm * 32 + mt * 16 + g;
                a[mt][0] = As[r0][kk + tig];
                a[mt][1] = As[r0 + 8][kk + tig];
                a[mt][2] = As[r0][kk + tig + 4];
                a[mt][3] = As[r0 + 8][kk + tig + 4];
            }
            #pragma unroll
            for (int nt = 0; nt < 8; nt++) {
                int n0 = wn * 64 + nt * 8 + g;
                unsigned b0 = Bs[n0][kk + tig];
                unsigned b1 = Bs[n0][kk + tig + 4];
                mma_tf32(acc[0][nt], a[0], b0, b1);
                mma_tf32(acc[1][nt], a[1], b0, b1);
            }
        }
        __syncthreads();
    }

    // epilogue
    #pragma unroll
    for (int mt = 0; mt < 2; mt++) {
        int r0 = bm + wm * 32 + mt * 16 + g;
        #pragma unroll
        for (int nt = 0; nt < 8; nt++) {
            int c0 = bn + wn * 64 + nt * 8 + 2 * tig;
            float bv0 = bias ? bias[c0] : 0.f;
            float bv1 = bias ? bias[c0 + 1] : 0.f;
            float v00 = acc[mt][nt][0] + bv0, v01 = acc[mt][nt][1] + bv1;
            float v10 = acc[mt][nt][2] + bv0, v11 = acc[mt][nt][3] + bv1;
            if (relu) {
                v00 = fmaxf(v00, 0.f); v01 = fmaxf(v01, 0.f);
                v10 = fmaxf(v10, 0.f); v11 = fmaxf(v11, 0.f);
            }
            *(float2*)(C + (size_t)r0 * N + c0)       = make_float2(v00, v01);
            *(float2*)(C + (size_t)(r0 + 8) * N + c0) = make_float2(v10, v11);
        }
    }
}

// ---------------- reparameterization + KLD ----------------
__global__ void k_z(const float* __restrict__ eps, const int* __restrict__ iftrain) {
    int idx = blockIdx.x * 256 + threadIdx.x;
    float m = g_MU[idx];
    float ls = fminf(g_LSR[idx], 10.f);
    float zz = (*iftrain > 0) ? (m + eps[idx] * expf(ls)) : m;
    g_Z[idx] = zz;
    float term = 1.f + 2.f * ls - m * m - expf(2.f * ls);
    float bs = block_sum<8>(term);
    if (threadIdx.x == 0) atomicAdd(&g_kld, (double)bs);
}

// ---------------- struct loss ----------------
__global__ __launch_bounds__(1024) void k_struct() {
    __shared__ float Zi[32][129];
    __shared__ float Zj[32][129];
    int i0 = blockIdx.y * 32, j0 = blockIdx.x * 32;
    int tid = threadIdx.y * 32 + threadIdx.x;
    for (int idx = tid; idx < 32 * 128; idx += 1024) {
        int r = idx >> 7, c = idx & 127;
        Zi[r][c] = g_Z[(size_t)(i0 + r) * H + c];
        Zj[r][c] = g_Z[(size_t)(j0 + r) * H + c];
    }
    __syncthreads();
    int ty = threadIdx.y, tx = threadIdx.x;
    float acc = 0.f;
    #pragma unroll 8
    for (int k = 0; k < 128; k++) acc += Zi[ty][k] * Zj[tx][k];
    int i = i0 + ty, j = j0 + tx;
    float adj = g_ADJ[(size_t)i * NNODE + j];
    float contrib = fmaxf(acc, 0.f) - acc * adj + log1pf(expf(-fabsf(acc)));
    float bs = block_sum<32>(contrib);
    if (tid == 0) atomicAdd(&g_struct, (double)bs);
}

// ---------------- build transformer input x ----------------
__global__ void k_xbuild(const float* __restrict__ w3, const float* __restrict__ b3) {
    int idx = blockIdx.x * 256 + threadIdx.x;
    int j = idx & 127;
    int tok = idx >> 7;
    int a = tok >> 7, h = tok & 127;
    float acc = b3[j];
    #pragma unroll
    for (int t = 0; t < OBS; t++)
        acc += g_OUTB[(size_t)((t << 8) + a) * H + h] * w3[j * OBS + t];
    g_X[idx] = acc;
}

// ---------------- attention (2 query rows / thread) ----------------
__global__ __launch_bounds__(128) void k_attn() {
    __shared__ float Ks[256][16];
    __shared__ float Vs[256][16];
    int bh = blockIdx.x;
    int b = bh >> 3, h = bh & 7;
    int t = threadIdx.x;
    #pragma unroll
    for (int rr = 0; rr < 2; rr++) {
        int row = t + rr * 128;
        const float* kptr = g_QKV + ((size_t)row * BB + b) * (3 * H) + H + h * DH;
        const float* vptr = kptr + H;
        #pragma unroll
        for (int d4 = 0; d4 < 4; d4++) {
            float4 kv = *(const float4*)(kptr + d4 * 4);
            Ks[row][d4 * 4 + 0] = kv.x; Ks[row][d4 * 4 + 1] = kv.y;
            Ks[row][d4 * 4 + 2] = kv.z; Ks[row][d4 * 4 + 3] = kv.w;
            float4 vv = *(const float4*)(vptr + d4 * 4);
            Vs[row][d4 * 4 + 0] = vv.x; Vs[row][d4 * 4 + 1] = vv.y;
            Vs[row][d4 * 4 + 2] = vv.z; Vs[row][d4 * 4 + 3] = vv.w;
        }
    }
    __syncthreads();
    float q[2][16], o[2][16] = {};
    float m[2], l[2];
    #pragma unroll
    for (int rr = 0; rr < 2; rr++) {
        int s = t + rr * 128;
        const float* qptr = g_QKV + ((size_t)s * BB + b) * (3 * H) + h * DH;
        #pragma unroll
        for (int d = 0; d < 16; d++) q[rr][d] = qptr[d];
        m[rr] = __int_as_float(0xff800000);
        l[rr] = 0.f;
    }
    for (int tt = 0; tt < 256; tt++) {
        float kr[16], vr[16];
        #pragma unroll
        for (int d4 = 0; d4 < 4; d4++) {
            float4 kv = *(const float4*)(&Ks[tt][d4 * 4]);
            kr[d4 * 4 + 0] = kv.x; kr[d4 * 4 + 1] = kv.y; kr[d4 * 4 + 2] = kv.z; kr[d4 * 4 + 3] = kv.w;
            float4 vv = *(const float4*)(&Vs[tt][d4 * 4]);
            vr[d4 * 4 + 0] = vv.x; vr[d4 * 4 + 1] = vv.y; vr[d4 * 4 + 2] = vv.z; vr[d4 * 4 + 3] = vv.w;
        }
        #pragma unroll
        for (int rr = 0; rr < 2; rr++) {
            float sc = 0.f;
            #pragma unroll
            for (int d = 0; d < 16; d++) sc += q[rr][d] * kr[d];
            sc *= 0.25f;
            float mn = fmaxf(m[rr], sc);
            float corr = __expf(m[rr] - mn);
            float p = __expf(sc - mn);
            l[rr] = l[rr] * corr + p;
            #pragma unroll
            for (int d = 0; d < 16; d++) o[rr][d] = o[rr][d] * corr + p * vr[d];
            m[rr] = mn;
        }
    }
    #pragma unroll
    for (int rr = 0; rr < 2; rr++) {
        int s = t + rr * 128;
        float invl = 1.f / l[rr];
        float* op = g_O + ((size_t)s * BB + b) * H + h * DH;
        #pragma unroll
        for (int d = 0; d < 16; d++) op[d] = o[rr][d] * invl;
    }
}

// ---------------- residual add + LayerNorm ----------------
__global__ void k_addln(const float* __restrict__ g, const float* __restrict__ bet) {
    int t = blockIdx.x, j = threadIdx.x;
    float v = g_X[(size_t)t * H + j] + g_TMP[(size_t)t * H + j];
    float mean = block_sum<4>(v) * (1.f / 128.f);
    float d = v - mean;
    float var = block_sum<4>(d * d) * (1.f / 128.f);
    g_X[(size_t)t * H + j] = d * (1.f / sqrtf(var + 1e-5f)) * g[j] + bet[j];
}

// ---------------- final projection + traj output + traj loss ----------------
__global__ void k_traj(const float* __restrict__ w4, const float* __restrict__ b4,
                       const float* __restrict__ w5, const float* __restrict__ b5,
                       const float* __restrict__ traj_in, float* __restrict__ out) {
    int tt = blockIdx.x >> 8;
    int a  = blockIdx.x & 255;
    int b  = threadIdx.x;
    int o = tt + (OBS - PRED);
    const float* xr = g_X + ((size_t)a * 128 + b) * 128;
    float acc = b4[o];
    #pragma unroll 8
    for (int j = 0; j < 128; j++) acc += xr[j] * w4[o * 128 + j];
    float s0 = block_sum<4>(acc * w5[b]);
    float s1 = block_sum<4>(acc * w5[128 + b]);
    if (b == 0) {
        float t0 = s0 + b5[0], t1 = s1 + b5[1];
        float y0 = traj_in[(OBS + tt) * (NAG * 2) + a * 2 + 0];
        float y1 = traj_in[(OBS + tt) * (NAG * 2) + a * 2 + 1];
        out[(tt * 256 + a) * 2 + 0] = t0;
        out[(tt * 256 + a) * 2 + 1] = t1;
        float d0 = t0 - y0, d1 = t1 - y1;
        atomicAdd(&g_traj, (double)sqrtf(d0 * d0 + d1 * d1));
    }
}

__global__ void k_final(float* __restrict__ out) {
    double kld = -0.5 * (g_kld / 2048.0);
    double st = g_struct / (2048.0 * 2048.0);
    double tl = g_traj / 256.0;
    out[PRED * NAG * FOUT] = (float)(tl + kld + st);
}

// ---------------- launch ----------------
extern "C" void kernel_launch(void* const* d_in, const int* in_sizes, int n_in,
                              void* d_out, int out_size) {
    const float* traj_in = (const float*)d_in[0];
    const float* adj_in  = (const float*)d_in[1];
    const float* eps     = (const float*)d_in[2];
    const float* pro1_w  = (const float*)d_in[3];
    const float* pro1_b  = (const float*)d_in[4];
    const float* pro2_w  = (const float*)d_in[5];
    const float* pro2_b  = (const float*)d_in[6];
    const float* mu_w    = (const float*)d_in[7];
    const float* mu_b    = (const float*)d_in[8];
    const float* ls_w    = (const float*)d_in[9];
    const float* ls_b    = (const float*)d_in[10];
    const float* gdl_w   = (const float*)d_in[11];
    const float* gdl_b   = (const float*)d_in[12];
    const float* pro3_w  = (const float*)d_in[13];
    const float* pro3_b  = (const float*)d_in[14];
    const float* pro4_w  = (const float*)d_in[15];
    const float* pro4_b  = (const float*)d_in[16];
    const float* pro5_w  = (const float*)d_in[17];
    const float* pro5_b  = (const float*)d_in[18];
    const float* qkv_w   = (const float*)d_in[19];
    const float* qkv_b   = (const float*)d_in[20];
    const float* out_w   = (const float*)d_in[21];
    const float* out_b   = (const float*)d_in[22];
    const float* ff1_w   = (const float*)d_in[23];
    const float* ff1_b   = (const float*)d_in[24];
    const float* ff2_w   = (const float*)d_in[25];
    const float* ff2_b   = (const float*)d_in[26];
    const float* ln1_g   = (const float*)d_in[27];
    const float* ln1_b   = (const float*)d_in[28];
    const float* ln2_g   = (const float*)d_in[29];
    const float* ln2_b   = (const float*)d_in[30];
    const int*   iftrain = (const int*)d_in[31];
    float* out = (float*)d_out;

    float *pENC, *pMLINT, *pLSLINT, *pAGG, *pMU, *pLSR, *pZ, *pOUTB, *pX, *pTMP, *pO, *pQKV, *pFFH;
    cudaGetSymbolAddress((void**)&pENC,    g_ENC);
    cudaGetSymbolAddress((void**)&pMLINT,  g_MLINT);
    cudaGetSymbolAddress((void**)&pLSLINT, g_LSLINT);
    cudaGetSymbolAddress((void**)&pAGG,    g_AGG);
    cudaGetSymbolAddress((void**)&pMU,     g_MU);
    cudaGetSymbolAddress((void**)&pLSR,    g_LSR);
    cudaGetSymbolAddress((void**)&pZ,      g_Z);
    cudaGetSymbolAddress((void**)&pOUTB,   g_OUTB);
    cudaGetSymbolAddress((void**)&pX,      g_X);
    cudaGetSymbolAddress((void**)&pTMP,    g_TMP);
    cudaGetSymbolAddress((void**)&pO,      g_O);
    cudaGetSymbolAddress((void**)&pQKV,    g_QKV);
    cudaGetSymbolAddress((void**)&pFFH,    g_FFH);

    // ---- graph-VAE front end ----
    k_init<<<8, 256>>>();
    k_minmax<<<512, 256>>>(adj_in);
    k_build<<<dim3(8, NNODE), 256>>>(adj_in);
    k_colsum<<<dim3(16, 16), 128>>>();
    k_dis<<<8, 256>>>();
    k_agg<<<dim3(64, 64), dim3(32, 32)>>>();
    k_enc<<<NNODE, 128>>>(traj_in, pro1_w, pro1_b, pro2_w, pro2_b);

    // mu_lin^T, ls_lin^T (fp32, stores transposed)
    k_gemm<<<dim3(2, 32), 256>>>(pENC, mu_w, mu_b, pMLINT, NNODE, H, H, 0, 1);
    k_gemm<<<dim3(2, 32), 256>>>(pENC, ls_w, ls_b, pLSLINT, NNODE, H, H, 0, 1);
    // MU = AGG @ mu_lin ; LSR = AGG @ ls_lin  (tf32 tensor cores)
    k_tgemm<<<dim3(1, 16), 256>>>(pAGG, pMLINT, nullptr, pMU, NNODE, H, NNODE, 0);
    k_tgemm<<<dim3(1, 16), 256>>>(pAGG, pLSLINT, nullptr, pLSR, NNODE, H, NNODE, 0);
    k_z<<<1024, 256>>>(eps, iftrain);
    k_struct<<<dim3(64, 64), dim3(32, 32)>>>();
    k_tgemm<<<dim3(1, 16), 256>>>(pZ, gdl_w, gdl_b, pOUTB, NNODE, H, H, 0);
    k_xbuild<<<16384, 256>>>(pro3_w, pro3_b);

    // ---- transformer ----
    for (int l = 0; l < NL; l++) {
        k_tgemm<<<dim3(3, 256), 256>>>(pX, qkv_w + (size_t)l * 3 * H * H, qkv_b + (size_t)l * 3 * H,
                                       pQKV, NTOK, 3 * H, H, 0);
        k_attn<<<BB * NH, 128>>>();
        k_tgemm<<<dim3(1, 256), 256>>>(pO, out_w + (size_t)l * H * H, out_b + (size_t)l * H,
                                       pTMP, NTOK, H, H, 0);
        k_addln<<<NTOK, 128>>>(ln1_g + l * H, ln1_b + l * H);
        k_tgemm<<<dim3(16, 256), 256>>>(pX, ff1_w + (size_t)l * FFD * H, ff1_b + (size_t)l * FFD,
                                        pFFH, NTOK, FFD, H, 1);
        k_tgemm<<<dim3(1, 256), 256>>>(pFFH, ff2_w + (size_t)l * H * FFD, ff2_b + (size_t)l * H,
                                       pTMP, NTOK, H, FFD, 0);
        k_addln<<<NTOK, 128>>>(ln2_g + l * H, ln2_b + l * H);
    }

    // ---- output + loss ----
    k_traj<<<PRED * NAG, 128>>>(pro4_w, pro4_b, pro5_w, pro5_b, traj_in, out);
    k_final<<<1, 1>>>(out);
}

// round 3
// speedup vs baseline: 2.3463x; 1.0065x over previous
#include <cuda_runtime.h>
#include <math.h>

#define OBS 8
#define PRED 4
#define NAG 256
#define FIN 2
#define FOUT 2
#define H 128
#define NH 8
#define DH 16
#define FFD 2048
#define NL 6
#define NNODE (OBS*NAG)        /* 2048 */
#define SEQ NAG                /* 256  */
#define BB H                   /* 128  */
#define NTOK (SEQ*BB)          /* 32768 */

// ---------------- scratch (device globals; no allocation) ----------------
static __device__ float g_ADJ[NNODE*NNODE];
static __device__ float g_AGG[NNODE*NNODE];
static __device__ float g_ENC[NNODE*H];
static __device__ float g_MLS[2*H*NNODE];      // [256][2048]: rows 0..127 mu_lin^T, 128..255 ls_lin^T
static __device__ float g_MULS[NNODE*2*H];     // [2048][256]: cols 0..127 mu, 128..255 logstd(raw)
static __device__ float g_Z[NNODE*H];
static __device__ float g_OUTB[NNODE*H];
static __device__ float g_X[NTOK*H];
static __device__ float g_O[NTOK*H];
static __device__ float g_QKV[NTOK*3*H];       // layout [3][8][128][256][16] = [p][h][b][s][d]
static __device__ float g_FFH[(size_t)NTOK*FFD];
static __device__ float g_COL[NNODE];
static __device__ float g_SELF[NNODE];
static __device__ float g_DIS[NNODE];
static __device__ float g_mn_acc, g_mx_acc;
static __device__ double g_kld, g_struct, g_traj;

// ---------------- helpers ----------------
__device__ __forceinline__ void atomicMinF(float* a, float v) {
    int* ai = (int*)a;
    int old = *ai;
    while (__int_as_float(old) > v) {
        int assumed = old;
        old = atomicCAS(ai, assumed, __float_as_int(v));
        if (old == assumed) break;
    }
}
__device__ __forceinline__ void atomicMaxF(float* a, float v) {
    int* ai = (int*)a;
    int old = *ai;
    while (__int_as_float(old) < v) {
        int assumed = old;
        old = atomicCAS(ai, assumed, __float_as_int(v));
        if (old == assumed) break;
    }
}

template<int NWARPS>
__device__ __forceinline__ float block_sum(float v) {
    __shared__ float w[NWARPS];
    int tid = threadIdx.x + threadIdx.y * blockDim.x;
    int lane = tid & 31, wid = tid >> 5;
    #pragma unroll
    for (int o = 16; o > 0; o >>= 1) v += __shfl_down_sync(0xffffffffu, v, o);
    if (lane == 0) w[wid] = v;
    __syncthreads();
    float r = 0.f;
    #pragma unroll
    for (int i = 0; i < NWARPS; i++) r += w[i];
    __syncthreads();
    return r;
}

__device__ __forceinline__ unsigned f2tf(float f) {
    unsigned u;
    asm("cvt.rna.tf32.f32 %0, %1;" : "=r"(u) : "f"(f));
    return u;
}

__device__ __forceinline__ void mma_tf32(float* c, const unsigned* a, unsigned b0, unsigned b1) {
    asm volatile(
        "mma.sync.aligned.m16n8k8.row.col.f32.tf32.tf32.f32 "
        "{%0,%1,%2,%3}, {%4,%5,%6,%7}, {%8,%9}, {%0,%1,%2,%3};"
        : "+f"(c[0]), "+f"(c[1]), "+f"(c[2]), "+f"(c[3])
        : "r"(a[0]), "r"(a[1]), "r"(a[2]), "r"(a[3]), "r"(b0), "r"(b1));
}

// ---------------- init ----------------
__global__ void k_init() {
    int i = blockIdx.x * 256 + threadIdx.x;
    if (i < NNODE) g_COL[i] = 0.f;
    if (i == 0) {
        g_mn_acc = __int_as_float(0x7f800000);
        g_mx_acc = __int_as_float(0xff800000);
        g_kld = 0.0; g_struct = 0.0; g_traj = 0.0;
    }
}

__global__ void k_zero(float* __restrict__ p, int n) {
    int i = blockIdx.x * 256 + threadIdx.x;
    if (i < n) p[i] = 0.f;
}

// ---------------- adjacency prep ----------------
__global__ void k_minmax(const float* __restrict__ adj) {
    const int n = OBS * NAG * NAG;
    float mn = __int_as_float(0x7f800000), mx = -mn;
    for (int i = blockIdx.x * blockDim.x + threadIdx.x; i < n; i += gridDim.x * blockDim.x) {
        float v = adj[i];
        mn = fminf(mn, v);
        mx = fmaxf(mx, v);
    }
    #pragma unroll
    for (int o = 16; o > 0; o >>= 1) {
        mn = fminf(mn, __shfl_down_sync(0xffffffffu, mn, o));
        mx = fmaxf(mx, __shfl_down_sync(0xffffffffu, mx, o));
    }
    __shared__ float smn[8], smx[8];
    int lane = threadIdx.x & 31, wid = threadIdx.x >> 5;
    if (lane == 0) { smn[wid] = mn; smx[wid] = mx; }
    __syncthreads();
    if (threadIdx.x == 0) {
        for (int w = 1; w < 8; w++) { mn = fminf(mn, smn[w]); mx = fmaxf(mx, smx[w]); }
        atomicMinF(&g_mn_acc, mn);
        atomicMaxF(&g_mx_acc, mx);
    }
}

__global__ void k_build(const float* __restrict__ adj) {
    float mn = fminf(g_mn_acc, 0.f);
    float mx = fmaxf(g_mx_acc, 0.f);
    float inv = 1.f / (mx - mn);
    int i = blockIdx.y;
    int j = blockIdx.x * 256 + threadIdx.x;
    int ti = i >> 8, tj = j >> 8;
    float a = (ti == tj) ? adj[(ti << 16) + ((i & 255) << 8) + (j & 255)] : 0.f;
    float v = (a - mn) * inv;
    g_ADJ[i * NNODE + j] = v;
    if (i == j) g_SELF[i] = (v == 0.f) ? 1.f : 0.f;
}

__global__ void k_colsum() {
    int j = blockIdx.x * 128 + threadIdx.x;
    int i0 = blockIdx.y * 32;
    float s = 0.f;
    for (int r = 0; r < 32; r++) s += g_ADJ[(size_t)(i0 + r) * NNODE + j];
    atomicAdd(&g_COL[j], s);
}

__global__ void k_dis() {
    int j = blockIdx.x * 256 + threadIdx.x;
    if (j < NNODE) {
        float deg = g_COL[j] + g_SELF[j];
        g_DIS[j] = (deg > 0.f) ? (1.f / sqrtf(deg)) : 0.f;
    }
}

__global__ void k_agg() {
    __shared__ float s[32][33];
    int i0 = blockIdx.y * 32, j0 = blockIdx.x * 32;
    int tx = threadIdx.x, ty = threadIdx.y;
    s[ty][tx] = g_ADJ[(size_t)(j0 + ty) * NNODE + (i0 + tx)];
    __syncthreads();
    int i = i0 + ty, j = j0 + tx;
    float v = s[tx][ty];
    if (i == j) v += g_SELF[i];
    g_AGG[(size_t)i * NNODE + j] = g_DIS[j] * v * g_DIS[i];
}

// ---------------- encoder ----------------
__global__ void k_enc(const float* __restrict__ traj,
                      const float* __restrict__ w1, const float* __restrict__ b1,
                      const float* __restrict__ w2, const float* __restrict__ b2) {
    int n = blockIdx.x, j = threadIdx.x;
    __shared__ float h1[128];
    float x0 = traj[n * 2], x1 = traj[n * 2 + 1];
    h1[j] = fmaxf(w1[j * 2] * x0 + w1[j * 2 + 1] * x1 + b1[j], 0.f);
    __syncthreads();
    float a = b2[j];
    #pragma unroll 8
    for (int k = 0; k < 128; k++) a += w2[j * 128 + k] * h1[k];
    g_ENC[n * 128 + j] = a;
}

// ---------------- fp32 SGEMM (small/transpose cases) ----------------
__global__ __launch_bounds__(256) void k_gemm(
    const float* __restrict__ A, const float* __restrict__ B,
    const float* __restrict__ bias, float* __restrict__ C,
    int M, int N, int K, int relu, int storeT)
{
    __shared__ float As[16][64];
    __shared__ float Bs[16][64];
    int bm = blockIdx.y * 64, bn = blockIdx.x * 64;
    int tid = threadIdx.x;
    int tx = tid & 15, ty = tid >> 4;
    int lr = tid >> 2, lc4 = (tid & 3) * 4;
    float acc[4][4] = {};
    for (int k0 = 0; k0 < K; k0 += 16) {
        float4 a4 = *(const float4*)(A + (size_t)(bm + lr) * K + k0 + lc4);
        float4 b4 = *(const float4*)(B + (size_t)(bn + lr) * K + k0 + lc4);
        As[lc4 + 0][lr] = a4.x; As[lc4 + 1][lr] = a4.y; As[lc4 + 2][lr] = a4.z; As[lc4 + 3][lr] = a4.w;
        Bs[lc4 + 0][lr] = b4.x; Bs[lc4 + 1][lr] = b4.y; Bs[lc4 + 2][lr] = b4.z; Bs[lc4 + 3][lr] = b4.w;
        __syncthreads();
        #pragma unroll
        for (int k = 0; k < 16; k++) {
            float ra[4], rb[4];
            #pragma unroll
            for (int i = 0; i < 4; i++) ra[i] = As[k][ty * 4 + i];
            #pragma unroll
            for (int j = 0; j < 4; j++) rb[j] = Bs[k][tx * 4 + j];
            #pragma unroll
            for (int i = 0; i < 4; i++)
                #pragma unroll
                for (int j = 0; j < 4; j++)
                    acc[i][j] += ra[i] * rb[j];
        }
        __syncthreads();
    }
    #pragma unroll
    for (int i = 0; i < 4; i++) {
        int row = bm + ty * 4 + i;
        #pragma unroll
        for (int j = 0; j < 4; j++) {
            int col = bn + tx * 4 + j;
            float v = acc[i][j];
            if (bias) v += bias[col];
            if (relu) v = fmaxf(v, 0.f);
            if (storeT) C[(size_t)col * M + row] = v;
            else        C[(size_t)row * N + col] = v;
        }
    }
}

// ---------------- tf32 tensor-core GEMM: C[M,N] = A[M,K] * B[N,K]^T ----------
// EPI: 0 = bias+optional relu; 1 = QKV scatter; 2 = bias+residual+LayerNorm (N==128);
//      3 = split-K atomicAdd (no bias)
// Smem columns are pair-permuted: orig col c -> (c&~7) + ((c&3)<<1) + ((c&4)>>2)
// so the MMA operand pairs (k, k+4) sit adjacent -> LDS.64.
template<int EPI>
__global__ __launch_bounds__(256, 2) void k_tgemm(
    const float* __restrict__ A, const float* __restrict__ B,
    const float* __restrict__ bias, float* __restrict__ C,
    int M, int N, int K, int relu,
    const float* __restrict__ gamma, const float* __restrict__ beta)
{
    __shared__ unsigned As[128][36];
    __shared__ unsigned Bs[128][36];
    int bm = blockIdx.y * 128, bn = blockIdx.x * 128;
    int tid = threadIdx.x;
    int warp = tid >> 5, lane = tid & 31;
    int wm = warp & 3, wn = warp >> 2;
    int g = lane >> 2, tig = lane & 3;
    int lr = tid >> 3, lc4 = (tid & 7) * 4;
    int p0 = (lc4 & ~7) + ((lc4 & 4) >> 2);

    int ks = K / gridDim.z;
    int k_begin = blockIdx.z * ks;
    int k_end = k_begin + ks;

    float acc[2][8][4] = {};
    float4 sa[4], sb[4];

    // prologue load
    #pragma unroll
    for (int i = 0; i < 4; i++) {
        int r = lr + i * 32;
        sa[i] = *(const float4*)(A + (size_t)(bm + r) * K + k_begin + lc4);
        sb[i] = *(const float4*)(B + (size_t)(bn + r) * K + k_begin + lc4);
    }
    #pragma unroll
    for (int i = 0; i < 4; i++) {
        int r = lr + i * 32;
        As[r][p0 + 0] = f2tf(sa[i].x); As[r][p0 + 2] = f2tf(sa[i].y);
        As[r][p0 + 4] = f2tf(sa[i].z); As[r][p0 + 6] = f2tf(sa[i].w);
        Bs[r][p0 + 0] = f2tf(sb[i].x); Bs[r][p0 + 2] = f2tf(sb[i].y);
        Bs[r][p0 + 4] = f2tf(sb[i].z); Bs[r][p0 + 6] = f2tf(sb[i].w);
    }
    __syncthreads();

    for (int k0 = k_begin + 32; k0 <= k_end; k0 += 32) {
        bool more = (k0 < k_end);
        if (more) {
            #pragma unroll
            for (int i = 0; i < 4; i++) {
                int r = lr + i * 32;
                sa[i] = *(const float4*)(A + (size_t)(bm + r) * K + k0 + lc4);
                sb[i] = *(const float4*)(B + (size_t)(bn + r) * K + k0 + lc4);
            }
        }
        #pragma unroll
        for (int kk = 0; kk < 32; kk += 8) {
            unsigned a[2][4];
            #pragma unroll
            for (int mt = 0; mt < 2; mt++) {
                int r0 = wm * 32 + mt * 16 + g;
                uint2 a01 = *(const uint2*)&As[r0][kk + 2 * tig];
                uint2 a23 = *(const uint2*)&As[r0 + 8][kk + 2 * tig];
                a[mt][0] = a01.x; a[mt][2] = a01.y;
                a[mt][1] = a23.x; a[mt][3] = a23.y;
            }
            #pragma unroll
            for (int nt = 0; nt < 8; nt++) {
                int n0 = wn * 64 + nt * 8 + g;
                uint2 bb = *(const uint2*)&Bs[n0][kk + 2 * tig];
                mma_tf32(acc[0][nt], a[0], bb.x, bb.y);
                mma_tf32(acc[1][nt], a[1], bb.x, bb.y);
            }
        }
        if (more) {
            __syncthreads();
            #pragma unroll
            for (int i = 0; i < 4; i++) {
                int r = lr + i * 32;
                As[r][p0 + 0] = f2tf(sa[i].x); As[r][p0 + 2] = f2tf(sa[i].y);
                As[r][p0 + 4] = f2tf(sa[i].z); As[r][p0 + 6] = f2tf(sa[i].w);
                Bs[r][p0 + 0] = f2tf(sb[i].x); Bs[r][p0 + 2] = f2tf(sb[i].y);
                Bs[r][p0 + 4] = f2tf(sb[i].z); Bs[r][p0 + 6] = f2tf(sb[i].w);
            }
            __syncthreads();
        }
    }

    // ---------------- epilogues ----------------
    if (EPI == 0) {
        #pragma unroll
        for (int mt = 0; mt < 2; mt++) {
            int r0 = bm + wm * 32 + mt * 16 + g;
            #pragma unroll
            for (int nt = 0; nt < 8; nt++) {
                int c0 = bn + wn * 64 + nt * 8 + 2 * tig;
                float bv0 = bias ? bias[c0] : 0.f;
                float bv1 = bias ? bias[c0 + 1] : 0.f;
                float v00 = acc[mt][nt][0] + bv0, v01 = acc[mt][nt][1] + bv1;
                float v10 = acc[mt][nt][2] + bv0, v11 = acc[mt][nt][3] + bv1;
                if (relu) {
                    v00 = fmaxf(v00, 0.f); v01 = fmaxf(v01, 0.f);
                    v10 = fmaxf(v10, 0.f); v11 = fmaxf(v11, 0.f);
                }
                *(float2*)(C + (size_t)r0 * N + c0)       = make_float2(v00, v01);
                *(float2*)(C + (size_t)(r0 + 8) * N + c0) = make_float2(v10, v11);
            }
        }
    } else if (EPI == 1) {
        int p = blockIdx.x;
        #pragma unroll
        for (int mt = 0; mt < 2; mt++) {
            int r0 = bm + wm * 32 + mt * 16 + g;
            int r1 = r0 + 8;
            #pragma unroll
            for (int nt = 0; nt < 8; nt++) {
                int rem = wn * 64 + nt * 8 + 2 * tig;
                int h = rem >> 4, d = rem & 15;
                int c0 = bn + rem;
                float bv0 = bias[c0], bv1 = bias[c0 + 1];
                size_t b0 = ((size_t)((p * 8 + h) * 128 + (r0 & 127)) * 256 + (r0 >> 7)) * 16 + d;
                size_t b1 = ((size_t)((p * 8 + h) * 128 + (r1 & 127)) * 256 + (r1 >> 7)) * 16 + d;
                *(float2*)(C + b0) = make_float2(acc[mt][nt][0] + bv0, acc[mt][nt][1] + bv1);
                *(float2*)(C + b1) = make_float2(acc[mt][nt][2] + bv0, acc[mt][nt][3] + bv1);
            }
        }
    } else if (EPI == 2) {
        // residual + LayerNorm over N==128 (full rows per block). C is X (in/out).
        float sums[2][2], sqs[2][2];
        #pragma unroll
        for (int mt = 0; mt < 2; mt++) { sums[mt][0] = sums[mt][1] = sqs[mt][0] = sqs[mt][1] = 0.f; }
        #pragma unroll
        for (int mt = 0; mt < 2; mt++) {
            int r0 = bm + wm * 32 + mt * 16 + g;
            #pragma unroll
            for (int nt = 0; nt < 8; nt++) {
                int c0 = wn * 64 + nt * 8 + 2 * tig;
                float bv0 = bias[c0], bv1 = bias[c0 + 1];
                float v00 = acc[mt][nt][0] + bv0 + C[(size_t)r0 * 128 + c0];
                float v01 = acc[mt][nt][1] + bv1 + C[(size_t)r0 * 128 + c0 + 1];
                float v10 = acc[mt][nt][2] + bv0 + C[(size_t)(r0 + 8) * 128 + c0];
                float v11 = acc[mt][nt][3] + bv1 + C[(size_t)(r0 + 8) * 128 + c0 + 1];
                acc[mt][nt][0] = v00; acc[mt][nt][1] = v01;
                acc[mt][nt][2] = v10; acc[mt][nt][3] = v11;
                sums[mt][0] += v00 + v01; sqs[mt][0] += v00 * v00 + v01 * v01;
                sums[mt][1] += v10 + v11; sqs[mt][1] += v10 * v10 + v11 * v11;
            }
        }
        #pragma unroll
        for (int mt = 0; mt < 2; mt++)
            #pragma unroll
            for (int rp = 0; rp < 2; rp++) {
                float s = sums[mt][rp], q = sqs[mt][rp];
                s += __shfl_xor_sync(0xffffffffu, s, 1); q += __shfl_xor_sync(0xffffffffu, q, 1);
                s += __shfl_xor_sync(0xffffffffu, s, 2); q += __shfl_xor_sync(0xffffffffu, q, 2);
                sums[mt][rp] = s; sqs[mt][rp] = q;
            }
        __syncthreads();               // done reading As/Bs; reuse as reduction buffer
        float* red = (float*)As;       // [warp][g][mt][rp][2] = 8*16*2*2*2 = 1024 floats
        if (tig == 0) {
            #pragma unroll
            for (int mt = 0; mt < 2; mt++)
                #pragma unroll
                for (int rp = 0; rp < 2; rp++) {
                    int ix = ((warp * 16 + g) * 4 + mt * 2 + rp) * 2;
                    red[ix] = sums[mt][rp]; red[ix + 1] = sqs[mt][rp];
                }
        }
        __syncthreads();
        float mean[2][2], inv[2][2];
        #pragma unroll
        for (int mt = 0; mt < 2; mt++)
            #pragma unroll
            for (int rp = 0; rp < 2; rp++) {
                int i0 = (((wm) * 16 + g) * 4 + mt * 2 + rp) * 2;
                int i1 = (((wm + 4) * 16 + g) * 4 + mt * 2 + rp) * 2;
                float s = red[i0] + red[i1];
                float q = red[i0 + 1] + red[i1 + 1];
                float m = s * (1.f / 128.f);
                float var = q * (1.f / 128.f) - m * m;
                mean[mt][rp] = m;
                inv[mt][rp] = rsqrtf(var + 1e-5f);
            }
        #pragma unroll
        for (int mt = 0; mt < 2; mt++) {
            int r0 = bm + wm * 32 + mt * 16 + g;
            #pragma unroll
            for (int nt = 0; nt < 8; nt++) {
                int c0 = wn * 64 + nt * 8 + 2 * tig;
                float g0 = gamma[c0], g1 = gamma[c0 + 1];
                float be0 = beta[c0], be1 = beta[c0 + 1];
                float v00 = (acc[mt][nt][0] - mean[mt][0]) * inv[mt][0] * g0 + be0;
                float v01 = (acc[mt][nt][1] - mean[mt][0]) * inv[mt][0] * g1 + be1;
                float v10 = (acc[mt][nt][2] - mean[mt][1]) * inv[mt][1] * g0 + be0;
                float v11 = (acc[mt][nt][3] - mean[mt][1]) * inv[mt][1] * g1 + be1;
                *(float2*)(C + (size_t)r0 * 128 + c0)       = make_float2(v00, v01);
                *(float2*)(C + (size_t)(r0 + 8) * 128 + c0) = make_float2(v10, v11);
            }
        }
    } else { // EPI == 3: split-K atomic accumulate
        #pragma unroll
        for (int mt = 0; mt < 2; mt++) {
            int r0 = bm + wm * 32 + mt * 16 + g;
            #pragma unroll
            for (int nt = 0; nt < 8; nt++) {
                int c0 = bn + wn * 64 + nt * 8 + 2 * tig;
                atomicAdd(C + (size_t)r0 * N + c0,           acc[mt][nt][0]);
                atomicAdd(C + (size_t)r0 * N + c0 + 1,       acc[mt][nt][1]);
                atomicAdd(C + (size_t)(r0 + 8) * N + c0,     acc[mt][nt][2]);
                atomicAdd(C + (size_t)(r0 + 8) * N + c0 + 1, acc[mt][nt][3]);
            }
        }
    }
}

// ---------------- reparameterization + KLD ----------------
__global__ void k_z(const float* __restrict__ eps, const int* __restrict__ iftrain) {
    int idx = blockIdx.x * 256 + threadIdx.x;   // 262144 total
    int i = idx >> 7, j = idx & 127;
    float m = g_MULS[(size_t)i * 256 + j];
    float ls = fminf(g_MULS[(size_t)i * 256 + 128 + j], 10.f);
    float zz = (*iftrain > 0) ? (m + eps[idx] * expf(ls)) : m;
    g_Z[idx] = zz;
    float term = 1.f + 2.f * ls - m * m - expf(2.f * ls);
    float bs = block_sum<8>(term);
    if (threadIdx.x == 0) atomicAdd(&g_kld, (double)bs);
}

// ---------------- struct loss: 64x64 tile, 2x2 per thread ----------------
__global__ __launch_bounds__(1024) void k_struct() {
    __shared__ float Zi[64][65];
    __shared__ float Zj[64][65];
    int i0 = blockIdx.y * 64, j0 = blockIdx.x * 64;
    int tid = threadIdx.y * 32 + threadIdx.x;
    int ty = threadIdx.y, tx = threadIdx.x;
    float acc[2][2] = {};
    for (int kc = 0; kc < 128; kc += 64) {
        __syncthreads();
        for (int idx = tid; idx < 64 * 64; idx += 1024) {
            int r = idx >> 6, c = idx & 63;
            Zi[r][c] = g_Z[(size_t)(i0 + r) * H + kc + c];
            Zj[r][c] = g_Z[(size_t)(j0 + r) * H + kc + c];
        }
        __syncthreads();
        #pragma unroll 8
        for (int k = 0; k < 64; k++) {
            float zi0 = Zi[ty * 2][k], zi1 = Zi[ty * 2 + 1][k];
            float zj0 = Zj[tx * 2][k], zj1 = Zj[tx * 2 + 1][k];
            acc[0][0] += zi0 * zj0; acc[0][1] += zi0 * zj1;
            acc[1][0] += zi1 * zj0; acc[1][1] += zi1 * zj1;
        }
    }
    float contrib = 0.f;
    #pragma unroll
    for (int ii = 0; ii < 2; ii++)
        #pragma unroll
        for (int jj = 0; jj < 2; jj++) {
            int i = i0 + ty * 2 + ii, j = j0 + tx * 2 + jj;
            float a = acc[ii][jj];
            float adj = g_ADJ[(size_t)i * NNODE + j];
            contrib += fmaxf(a, 0.f) - a * adj + log1pf(expf(-fabsf(a)));
        }
    float bs = block_sum<32>(contrib);
    if (tid == 0) atomicAdd(&g_struct, (double)bs);
}

// ---------------- build transformer input x ----------------
__global__ void k_xbuild(const float* __restrict__ w3, const float* __restrict__ b3) {
    int idx = blockIdx.x * 256 + threadIdx.x;
    int j = idx & 127;
    int tok = idx >> 7;
    int a = tok >> 7, h = tok & 127;
    float acc = b3[j];
    #pragma unroll
    for (int t = 0; t < OBS; t++)
        acc += g_OUTB[(size_t)((t << 8) + a) * H + h] * w3[j * OBS + t];
    g_X[idx] = acc;
}

// ---------------- attention: QKV in [p][h][b][s][d] layout ----------------
__global__ __launch_bounds__(128) void k_attn() {
    __shared__ float Ks[256 * 16];
    __shared__ float Vs[256 * 16];
    int bh = blockIdx.x;
    int b = bh >> 3, h = bh & 7;
    int t = threadIdx.x;
    const float* Qb = g_QKV + (size_t)((0 * 8 + h) * 128 + b) * 4096;
    const float* Kb = g_QKV + (size_t)((1 * 8 + h) * 128 + b) * 4096;
    const float* Vb = g_QKV + (size_t)((2 * 8 + h) * 128 + b) * 4096;
    for (int i = t; i < 1024; i += 128) {
        ((float4*)Ks)[i] = ((const float4*)Kb)[i];
        ((float4*)Vs)[i] = ((const float4*)Vb)[i];
    }
    __syncthreads();
    float q[2][16], o[2][16] = {};
    float m[2], l[2];
    #pragma unroll
    for (int rr = 0; rr < 2; rr++) {
        int s = t + rr * 128;
        const float* qp = Qb + s * 16;
        #pragma unroll
        for (int d4 = 0; d4 < 4; d4++) {
            float4 qq = *(const float4*)(qp + d4 * 4);
            q[rr][d4 * 4 + 0] = qq.x; q[rr][d4 * 4 + 1] = qq.y;
            q[rr][d4 * 4 + 2] = qq.z; q[rr][d4 * 4 + 3] = qq.w;
        }
        m[rr] = __int_as_float(0xff800000);
        l[rr] = 0.f;
    }
    for (int tt = 0; tt < 256; tt++) {
        float kr[16], vr[16];
        #pragma unroll
        for (int d4 = 0; d4 < 4; d4++) {
            float4 kv = *(const float4*)(&Ks[tt * 16 + d4 * 4]);
            kr[d4 * 4 + 0] = kv.x; kr[d4 * 4 + 1] = kv.y; kr[d4 * 4 + 2] = kv.z; kr[d4 * 4 + 3] = kv.w;
            float4 vv = *(const float4*)(&Vs[tt * 16 + d4 * 4]);
            vr[d4 * 4 + 0] = vv.x; vr[d4 * 4 + 1] = vv.y; vr[d4 * 4 + 2] = vv.z; vr[d4 * 4 + 3] = vv.w;
        }
        #pragma unroll
        for (int rr = 0; rr < 2; rr++) {
            float sc = 0.f;
            #pragma unroll
            for (int d = 0; d < 16; d++) sc += q[rr][d] * kr[d];
            sc *= 0.25f;
            float mn = fmaxf(m[rr], sc);
            float corr = __expf(m[rr] - mn);
            float p = __expf(sc - mn);
            l[rr] = l[rr] * corr + p;
            #pragma unroll
            for (int d = 0; d < 16; d++) o[rr][d] = o[rr][d] * corr + p * vr[d];
            m[rr] = mn;
        }
    }
    #pragma unroll
    for (int rr = 0; rr < 2; rr++) {
        int s = t + rr * 128;
        float invl = 1.f / l[rr];
        float* op = g_O + ((size_t)s * BB + b) * H + h * DH;
        #pragma unroll
        for (int d = 0; d < 16; d++) op[d] = o[rr][d] * invl;
    }
}

// ---------------- final projection + traj output + traj loss ----------------
__global__ void k_traj(const float* __restrict__ w4, const float* __restrict__ b4,
                       const float* __restrict__ w5, const float* __restrict__ b5,
                       const float* __restrict__ traj_in, float* __restrict__ out) {
    int tt = blockIdx.x >> 8;
    int a  = blockIdx.x & 255;
    int b  = threadIdx.x;
    int o = tt + (OBS - PRED);
    const float* xr = g_X + ((size_t)a * 128 + b) * 128;
    float acc = b4[o];
    #pragma unroll 8
    for (int j = 0; j < 128; j++) acc += xr[j] * w4[o * 128 + j];
    float s0 = block_sum<4>(acc * w5[b]);
    float s1 = block_sum<4>(acc * w5[128 + b]);
    if (b == 0) {
        float t0 = s0 + b5[0], t1 = s1 + b5[1];
        float y0 = traj_in[(OBS + tt) * (NAG * 2) + a * 2 + 0];
        float y1 = traj_in[(OBS + tt) * (NAG * 2) + a * 2 + 1];
        out[(tt * 256 + a) * 2 + 0] = t0;
        out[(tt * 256 + a) * 2 + 1] = t1;
        float d0 = t0 - y0, d1 = t1 - y1;
        atomicAdd(&g_traj, (double)sqrtf(d0 * d0 + d1 * d1));
    }
}

__global__ void k_final(float* __restrict__ out) {
    double kld = -0.5 * (g_kld / 2048.0);
    double st = g_struct / (2048.0 * 2048.0);
    double tl = g_traj / 256.0;
    out[PRED * NAG * FOUT] = (float)(tl + kld + st);
}

// ---------------- launch ----------------
extern "C" void kernel_launch(void* const* d_in, const int* in_sizes, int n_in,
                              void* d_out, int out_size) {
    const float* traj_in = (const float*)d_in[0];
    const float* adj_in  = (const float*)d_in[1];
    const float* eps     = (const float*)d_in[2];
    const float* pro1_w  = (const float*)d_in[3];
    const float* pro1_b  = (const float*)d_in[4];
    const float* pro2_w  = (const float*)d_in[5];
    const float* pro2_b  = (const float*)d_in[6];
    const float* mu_w    = (const float*)d_in[7];
    const float* mu_b    = (const float*)d_in[8];
    const float* ls_w    = (const float*)d_in[9];
    const float* ls_b    = (const float*)d_in[10];
    const float* gdl_w   = (const float*)d_in[11];
    const float* gdl_b   = (const float*)d_in[12];
    const float* pro3_w  = (const float*)d_in[13];
    const float* pro3_b  = (const float*)d_in[14];
    const float* pro4_w  = (const float*)d_in[15];
    const float* pro4_b  = (const float*)d_in[16];
    const float* pro5_w  = (const float*)d_in[17];
    const float* pro5_b  = (const float*)d_in[18];
    const float* qkv_w   = (const float*)d_in[19];
    const float* qkv_b   = (const float*)d_in[20];
    const float* out_w   = (const float*)d_in[21];
    const float* out_b   = (const float*)d_in[22];
    const float* ff1_w   = (const float*)d_in[23];
    const float* ff1_b   = (const float*)d_in[24];
    const float* ff2_w   = (const float*)d_in[25];
    const float* ff2_b   = (const float*)d_in[26];
    const float* ln1_g   = (const float*)d_in[27];
    const float* ln1_b   = (const float*)d_in[28];
    const float* ln2_g   = (const float*)d_in[29];
    const float* ln2_b   = (const float*)d_in[30];
    const int*   iftrain = (const int*)d_in[31];
    float* out = (float*)d_out;

    float *pENC, *pMLS, *pMULS, *pAGG, *pZ, *pOUTB, *pX, *pO, *pQKV, *pFFH;
    cudaGetSymbolAddress((void**)&pENC,  g_ENC);
    cudaGetSymbolAddress((void**)&pMLS,  g_MLS);
    cudaGetSymbolAddress((void**)&pMULS, g_MULS);
    cudaGetSymbolAddress((void**)&pAGG,  g_AGG);
    cudaGetSymbolAddress((void**)&pZ,    g_Z);
    cudaGetSymbolAddress((void**)&pOUTB, g_OUTB);
    cudaGetSymbolAddress((void**)&pX,    g_X);
    cudaGetSymbolAddress((void**)&pO,    g_O);
    cudaGetSymbolAddress((void**)&pQKV,  g_QKV);
    cudaGetSymbolAddress((void**)&pFFH,  g_FFH);

    // ---- graph-VAE front end ----
    k_init<<<8, 256>>>();
    k_zero<<<(NNODE * 256 + 255) / 256, 256>>>(pMULS, NNODE * 256);
    k_minmax<<<512, 256>>>(adj_in);
    k_build<<<dim3(8, NNODE), 256>>>(adj_in);
    k_colsum<<<dim3(16, 64), 128>>>();
    k_dis<<<8, 256>>>();
    k_agg<<<dim3(64, 64), dim3(32, 32)>>>();
    k_enc<<<NNODE, 128>>>(traj_in, pro1_w, pro1_b, pro2_w, pro2_b);

    // mu_lin^T / ls_lin^T packed into one [256][2048] buffer
    k_gemm<<<dim3(2, 32), 256>>>(pENC, mu_w, mu_b, pMLS, NNODE, H, H, 0, 1);
    k_gemm<<<dim3(2, 32), 256>>>(pENC, ls_w, ls_b, pMLS + (size_t)128 * NNODE, NNODE, H, H, 0, 1);
    // [MU | LSR] = AGG @ [mu_lin | ls_lin]  (single split-K tf32 GEMM)
    k_tgemm<3><<<dim3(2, 16, 8), 256>>>(pAGG, pMLS, nullptr, pMULS, NNODE, 256, NNODE, 0, nullptr, nullptr);
    k_z<<<1024, 256>>>(eps, iftrain);
    k_struct<<<dim3(32, 32), dim3(32, 32)>>>();
    k_tgemm<0><<<dim3(1, 16), 256>>>(pZ, gdl_w, gdl_b, pOUTB, NNODE, H, H, 0, nullptr, nullptr);
    k_xbuild<<<16384, 256>>>(pro3_w, pro3_b);

    // ---- transformer ----
    for (int l = 0; l < NL; l++) {
        k_tgemm<1><<<dim3(3, 256), 256>>>(pX, qkv_w + (size_t)l * 3 * H * H, qkv_b + (size_t)l * 3 * H,
                                          pQKV, NTOK, 3 * H, H, 0, nullptr, nullptr);
        k_attn<<<BB * NH, 128>>>();
        k_tgemm<2><<<dim3(1, 256), 256>>>(pO, out_w + (size_t)l * H * H, out_b + (size_t)l * H,
                                          pX, NTOK, H, H, 0, ln1_g + l * H, ln1_b + l * H);
        k_tgemm<0><<<dim3(16, 256), 256>>>(pX, ff1_w + (size_t)l * FFD * H, ff1_b + (size_t)l * FFD,
                                           pFFH, NTOK, FFD, H, 1, nullptr, nullptr);
        k_tgemm<2><<<dim3(1, 256), 256>>>(pFFH, ff2_w + (size_t)l * H * FFD, ff2_b + (size_t)l * H,
                                          pX, NTOK, H, FFD, 0, ln2_g + l * H, ln2_b + l * H);
    }

    // ---- output + loss ----
    k_traj<<<PRED * NAG, 128>>>(pro4_w, pro4_b, pro5_w, pro5_b, traj_in, out);
    k_final<<<1, 1>>>(out);
}

// round 4
// speedup vs baseline: 3.0658x; 1.3066x over previous
#include <cuda_runtime.h>
#include <cuda_fp16.h>
#include <math.h>

#define OBS 8
#define PRED 4
#define NAG 256
#define FIN 2
#define FOUT 2
#define H 128
#define NH 8
#define DH 16
#define FFD 2048
#define NL 6
#define NNODE (OBS*NAG)        /* 2048 */
#define SEQ NAG                /* 256  */
#define BB H                   /* 128  */
#define NTOK (SEQ*BB)          /* 32768 */

// ---------------- scratch (device globals; no allocation) ----------------
static __device__ float  g_ADJ[NNODE*NNODE];
static __device__ __half g_AGGH[NNODE*NNODE];
static __device__ float  g_ENC[NNODE*H];
static __device__ __half g_MLSH[2*H*NNODE];     // [256][2048] rows 0..127 mu^T, 128..255 ls^T
static __device__ float  g_MULS[NNODE*2*H];     // [2048][256] cols 0..127 mu, 128..255 logstd raw
static __device__ float  g_Z[NNODE*H];
static __device__ __half g_ZH[NNODE*H];
static __device__ float  g_OUTB[NNODE*H];
static __device__ float  g_X[NTOK*H];
static __device__ __half g_XH[NTOK*H];
static __device__ __half g_OH[NTOK*H];
static __device__ __half g_QKVH[NTOK*3*H];      // [p][h][b][s][d]
static __device__ __half g_FFHH[(size_t)NTOK*FFD];
static __device__ __half g_WQKVH[NL*3*H*H];
static __device__ __half g_WOUTH[NL*H*H];
static __device__ __half g_WFF1H[(size_t)NL*FFD*H];
static __device__ __half g_WFF2H[(size_t)NL*H*FFD];
static __device__ __half g_WGDLH[H*H];
static __device__ float  g_COL[NNODE];
static __device__ float  g_SELF[NNODE];
static __device__ float  g_DIS[NNODE];
static __device__ float  g_mn_acc, g_mx_acc;
static __device__ double g_kld, g_struct, g_traj;

// ---------------- helpers ----------------
__device__ __forceinline__ void atomicMinF(float* a, float v) {
    int* ai = (int*)a; int old = *ai;
    while (__int_as_float(old) > v) {
        int assumed = old;
        old = atomicCAS(ai, assumed, __float_as_int(v));
        if (old == assumed) break;
    }
}
__device__ __forceinline__ void atomicMaxF(float* a, float v) {
    int* ai = (int*)a; int old = *ai;
    while (__int_as_float(old) < v) {
        int assumed = old;
        old = atomicCAS(ai, assumed, __float_as_int(v));
        if (old == assumed) break;
    }
}

template<int NWARPS>
__device__ __forceinline__ float block_sum(float v) {
    __shared__ float w[NWARPS];
    int tid = threadIdx.x + threadIdx.y * blockDim.x;
    int lane = tid & 31, wid = tid >> 5;
    #pragma unroll
    for (int o = 16; o > 0; o >>= 1) v += __shfl_down_sync(0xffffffffu, v, o);
    if (lane == 0) w[wid] = v;
    __syncthreads();
    float r = 0.f;
    #pragma unroll
    for (int i = 0; i < NWARPS; i++) r += w[i];
    __syncthreads();
    return r;
}

__device__ __forceinline__ void mma_f16(float* c, const unsigned* a, unsigned b0, unsigned b1) {
    asm volatile(
        "mma.sync.aligned.m16n8k16.row.col.f32.f16.f16.f32 "
        "{%0,%1,%2,%3}, {%4,%5,%6,%7}, {%8,%9}, {%0,%1,%2,%3};"
        : "+f"(c[0]), "+f"(c[1]), "+f"(c[2]), "+f"(c[3])
        : "r"(a[0]), "r"(a[1]), "r"(a[2]), "r"(a[3]), "r"(b0), "r"(b1));
}

// ---------------- init / convert ----------------
__global__ void k_init() {
    int i = blockIdx.x * 256 + threadIdx.x;
    if (i < NNODE) g_COL[i] = 0.f;
    if (i == 0) {
        g_mn_acc = __int_as_float(0x7f800000);
        g_mx_acc = __int_as_float(0xff800000);
        g_kld = 0.0; g_struct = 0.0; g_traj = 0.0;
    }
}
__global__ void k_zero(float* __restrict__ p, int n) {
    int i = blockIdx.x * 256 + threadIdx.x;
    if (i < n) p[i] = 0.f;
}
__global__ void k_f2h(const float* __restrict__ s, __half* __restrict__ d, int n) {
    int i = blockIdx.x * 256 + threadIdx.x;
    if (i < n) d[i] = __float2half(s[i]);
}

// ---------------- adjacency prep ----------------
__global__ void k_minmax(const float* __restrict__ adj) {
    const int n = OBS * NAG * NAG;
    float mn = __int_as_float(0x7f800000), mx = -mn;
    for (int i = blockIdx.x * blockDim.x + threadIdx.x; i < n; i += gridDim.x * blockDim.x) {
        float v = adj[i];
        mn = fminf(mn, v); mx = fmaxf(mx, v);
    }
    #pragma unroll
    for (int o = 16; o > 0; o >>= 1) {
        mn = fminf(mn, __shfl_down_sync(0xffffffffu, mn, o));
        mx = fmaxf(mx, __shfl_down_sync(0xffffffffu, mx, o));
    }
    __shared__ float smn[8], smx[8];
    int lane = threadIdx.x & 31, wid = threadIdx.x >> 5;
    if (lane == 0) { smn[wid] = mn; smx[wid] = mx; }
    __syncthreads();
    if (threadIdx.x == 0) {
        for (int w = 1; w < 8; w++) { mn = fminf(mn, smn[w]); mx = fmaxf(mx, smx[w]); }
        atomicMinF(&g_mn_acc, mn);
        atomicMaxF(&g_mx_acc, mx);
    }
}

__global__ void k_build(const float* __restrict__ adj) {
    float mn = fminf(g_mn_acc, 0.f);
    float mx = fmaxf(g_mx_acc, 0.f);
    float inv = 1.f / (mx - mn);
    int i = blockIdx.y;
    int j = blockIdx.x * 256 + threadIdx.x;
    int ti = i >> 8, tj = j >> 8;
    float a = (ti == tj) ? adj[(ti << 16) + ((i & 255) << 8) + (j & 255)] : 0.f;
    float v = (a - mn) * inv;
    g_ADJ[i * NNODE + j] = v;
    if (i == j) g_SELF[i] = (v == 0.f) ? 1.f : 0.f;
}

__global__ void k_colsum() {
    int j = blockIdx.x * 128 + threadIdx.x;
    int i0 = blockIdx.y * 32;
    float s = 0.f;
    for (int r = 0; r < 32; r++) s += g_ADJ[(size_t)(i0 + r) * NNODE + j];
    atomicAdd(&g_COL[j], s);
}

__global__ void k_dis() {
    int j = blockIdx.x * 256 + threadIdx.x;
    if (j < NNODE) {
        float deg = g_COL[j] + g_SELF[j];
        g_DIS[j] = (deg > 0.f) ? (1.f / sqrtf(deg)) : 0.f;
    }
}

// agg[i,j] = dis[j] * A_sl[j,i] * dis[i]  (written as half)
__global__ void k_agg() {
    __shared__ float s[32][33];
    int i0 = blockIdx.y * 32, j0 = blockIdx.x * 32;
    int tx = threadIdx.x, ty = threadIdx.y;
    s[ty][tx] = g_ADJ[(size_t)(j0 + ty) * NNODE + (i0 + tx)];
    __syncthreads();
    int i = i0 + ty, j = j0 + tx;
    float v = s[tx][ty];
    if (i == j) v += g_SELF[i];
    g_AGGH[(size_t)i * NNODE + j] = __float2half(g_DIS[j] * v * g_DIS[i]);
}

// ---------------- encoder ----------------
__global__ void k_enc(const float* __restrict__ traj,
                      const float* __restrict__ w1, const float* __restrict__ b1,
                      const float* __restrict__ w2, const float* __restrict__ b2) {
    int n = blockIdx.x, j = threadIdx.x;
    __shared__ float h1[128];
    float x0 = traj[n * 2], x1 = traj[n * 2 + 1];
    h1[j] = fmaxf(w1[j * 2] * x0 + w1[j * 2 + 1] * x1 + b1[j], 0.f);
    __syncthreads();
    float a = b2[j];
    #pragma unroll 8
    for (int k = 0; k < 128; k++) a += w2[j * 128 + k] * h1[k];
    g_ENC[n * 128 + j] = a;
}

// ---------------- fp32 SIMT GEMM, transposed half output (MLS) ----------------
__global__ __launch_bounds__(256) void k_gemm(
    const float* __restrict__ A, const float* __restrict__ B,
    const float* __restrict__ bias, __half* __restrict__ hC,
    int M, int N, int K)
{
    __shared__ float As[16][64];
    __shared__ float Bs[16][64];
    int bm = blockIdx.y * 64, bn = blockIdx.x * 64;
    int tid = threadIdx.x;
    int tx = tid & 15, ty = tid >> 4;
    int lr = tid >> 2, lc4 = (tid & 3) * 4;
    float acc[4][4] = {};
    for (int k0 = 0; k0 < K; k0 += 16) {
        float4 a4 = *(const float4*)(A + (size_t)(bm + lr) * K + k0 + lc4);
        float4 b4 = *(const float4*)(B + (size_t)(bn + lr) * K + k0 + lc4);
        As[lc4 + 0][lr] = a4.x; As[lc4 + 1][lr] = a4.y; As[lc4 + 2][lr] = a4.z; As[lc4 + 3][lr] = a4.w;
        Bs[lc4 + 0][lr] = b4.x; Bs[lc4 + 1][lr] = b4.y; Bs[lc4 + 2][lr] = b4.z; Bs[lc4 + 3][lr] = b4.w;
        __syncthreads();
        #pragma unroll
        for (int k = 0; k < 16; k++) {
            float ra[4], rb[4];
            #pragma unroll
            for (int i = 0; i < 4; i++) ra[i] = As[k][ty * 4 + i];
            #pragma unroll
            for (int j = 0; j < 4; j++) rb[j] = Bs[k][tx * 4 + j];
            #pragma unroll
            for (int i = 0; i < 4; i++)
                #pragma unroll
                for (int j = 0; j < 4; j++)
                    acc[i][j] += ra[i] * rb[j];
        }
        __syncthreads();
    }
    #pragma unroll
    for (int i = 0; i < 4; i++) {
        int row = bm + ty * 4 + i;
        #pragma unroll
        for (int j = 0; j < 4; j++) {
            int col = bn + tx * 4 + j;
            hC[(size_t)col * M + row] = __float2half(acc[i][j] + bias[col]);
        }
    }
}

// ---------------- fp16 tensor-core GEMM: C[M,N] = A[M,K] * B[N,K]^T ----------
// EPI: 0 = bias -> fp32 C; 1 = QKV scatter -> half Ch; 2 = bias+residual+LN (N==128)
//      -> fp32 C + half Ch; 3 = split-K atomicAdd -> fp32 C; 4 = bias+relu -> half Ch
// Smem: per row (32 halves) 8 granules of 8B; granule (ks,q) holds k-pairs (q,q+4)
// of k-step ks; physical granule = logical ^ ((row&2)<<1). Conflict-free STS.128/LDS.64.
template<int EPI>
__global__ __launch_bounds__(256, 2) void k_hgemm(
    const __half* __restrict__ A, const __half* __restrict__ B,
    const float* __restrict__ bias, float* __restrict__ C, __half* __restrict__ Ch,
    int M, int N, int K, int relu,
    const float* __restrict__ gamma, const float* __restrict__ beta)
{
    __shared__ unsigned As[128][16];
    __shared__ unsigned Bs[128][16];
    int bm = blockIdx.y * 128, bn = blockIdx.x * 128;
    int tid = threadIdx.x;
    int warp = tid >> 5, lane = tid & 31;
    int wm = warp & 3, wn = warp >> 2;
    int g = lane >> 2, tig = lane & 3;
    int lr = tid >> 1, lks = tid & 1;
    int lswz = (lr >> 1) & 1;               // (lr&2)>>1
    int sbase = 8 * (lks ^ lswz);           // uint index of thread's 32B store slot
    int gswz = ((g >> 1) & 1) * 4;          // granule XOR for fragment loads

    int ksz = K / gridDim.z;
    int k_begin = blockIdx.z * ksz;
    int k_end = k_begin + ksz;

    float acc[2][8][4] = {};
    uint4 ua0, ua1, ub0, ub1;

    const uint4* gA = (const uint4*)(A + (size_t)(bm + lr) * K + k_begin + 16 * lks);
    const uint4* gB = (const uint4*)(B + (size_t)(bn + lr) * K + k_begin + 16 * lks);
    ua0 = gA[0]; ua1 = gA[1];
    ub0 = gB[0]; ub1 = gB[1];
    {
        uint4* sA = (uint4*)&As[lr][sbase];
        sA[0] = make_uint4(ua0.x, ua1.x, ua0.y, ua1.y);
        sA[1] = make_uint4(ua0.z, ua1.z, ua0.w, ua1.w);
        uint4* sB = (uint4*)&Bs[lr][sbase];
        sB[0] = make_uint4(ub0.x, ub1.x, ub0.y, ub1.y);
        sB[1] = make_uint4(ub0.z, ub1.z, ub0.w, ub1.w);
    }
    __syncthreads();

    for (int k0 = k_begin + 32; k0 <= k_end; k0 += 32) {
        bool more = (k0 < k_end);
        if (more) {
            const uint4* nA = (const uint4*)(A + (size_t)(bm + lr) * K + k0 + 16 * lks);
            const uint4* nB = (const uint4*)(B + (size_t)(bn + lr) * K + k0 + 16 * lks);
            ua0 = nA[0]; ua1 = nA[1];
            ub0 = nB[0]; ub1 = nB[1];
        }
        #pragma unroll
        for (int ks = 0; ks < 2; ks++) {
            int gi = 2 * ((4 * ks + tig) ^ gswz);
            unsigned a[2][4];
            #pragma unroll
            for (int mt = 0; mt < 2; mt++) {
                int r0 = wm * 32 + mt * 16 + g;
                uint2 alo = *(const uint2*)&As[r0][gi];
                uint2 ahi = *(const uint2*)&As[r0 + 8][gi];
                a[mt][0] = alo.x; a[mt][1] = ahi.x;
                a[mt][2] = alo.y; a[mt][3] = ahi.y;
            }
            #pragma unroll
            for (int nt = 0; nt < 8; nt++) {
                int n0 = wn * 64 + nt * 8 + g;
                uint2 bb = *(const uint2*)&Bs[n0][gi];
                mma_f16(acc[0][nt], a[0], bb.x, bb.y);
                mma_f16(acc[1][nt], a[1], bb.x, bb.y);
            }
        }
        if (more) {
            __syncthreads();
            uint4* sA = (uint4*)&As[lr][sbase];
            sA[0] = make_uint4(ua0.x, ua1.x, ua0.y, ua1.y);
            sA[1] = make_uint4(ua0.z, ua1.z, ua0.w, ua1.w);
            uint4* sB = (uint4*)&Bs[lr][sbase];
            sB[0] = make_uint4(ub0.x, ub1.x, ub0.y, ub1.y);
            sB[1] = make_uint4(ub0.z, ub1.z, ub0.w, ub1.w);
            __syncthreads();
        }
    }

    // ---------------- epilogues ----------------
    if (EPI == 0) {
        #pragma unroll
        for (int mt = 0; mt < 2; mt++) {
            int r0 = bm + wm * 32 + mt * 16 + g;
            #pragma unroll
            for (int nt = 0; nt < 8; nt++) {
                int c0 = bn + wn * 64 + nt * 8 + 2 * tig;
                float bv0 = bias[c0], bv1 = bias[c0 + 1];
                *(float2*)(C + (size_t)r0 * N + c0) =
                    make_float2(acc[mt][nt][0] + bv0, acc[mt][nt][1] + bv1);
                *(float2*)(C + (size_t)(r0 + 8) * N + c0) =
                    make_float2(acc[mt][nt][2] + bv0, acc[mt][nt][3] + bv1);
            }
        }
    } else if (EPI == 1) {
        int p = blockIdx.x;
        #pragma unroll
        for (int mt = 0; mt < 2; mt++) {
            int r0 = bm + wm * 32 + mt * 16 + g;
            int r1 = r0 + 8;
            #pragma unroll
            for (int nt = 0; nt < 8; nt++) {
                int rem = wn * 64 + nt * 8 + 2 * tig;
                int h = rem >> 4, d = rem & 15;
                int c0 = bn + rem;
                float bv0 = bias[c0], bv1 = bias[c0 + 1];
                size_t b0 = ((size_t)((p * 8 + h) * 128 + (r0 & 127)) * 256 + (r0 >> 7)) * 16 + d;
                size_t b1 = ((size_t)((p * 8 + h) * 128 + (r1 & 127)) * 256 + (r1 >> 7)) * 16 + d;
                *(__half2*)(Ch + b0) = __floats2half2_rn(acc[mt][nt][0] + bv0, acc[mt][nt][1] + bv1);
                *(__half2*)(Ch + b1) = __floats2half2_rn(acc[mt][nt][2] + bv0, acc[mt][nt][3] + bv1);
            }
        }
    } else if (EPI == 2) {
        float sums[2][2], sqs[2][2];
        #pragma unroll
        for (int mt = 0; mt < 2; mt++) { sums[mt][0] = sums[mt][1] = sqs[mt][0] = sqs[mt][1] = 0.f; }
        #pragma unroll
        for (int mt = 0; mt < 2; mt++) {
            int r0 = bm + wm * 32 + mt * 16 + g;
            #pragma unroll
            for (int nt = 0; nt < 8; nt++) {
                int c0 = wn * 64 + nt * 8 + 2 * tig;
                float bv0 = bias[c0], bv1 = bias[c0 + 1];
                float v00 = acc[mt][nt][0] + bv0 + C[(size_t)r0 * 128 + c0];
                float v01 = acc[mt][nt][1] + bv1 + C[(size_t)r0 * 128 + c0 + 1];
                float v10 = acc[mt][nt][2] + bv0 + C[(size_t)(r0 + 8) * 128 + c0];
                float v11 = acc[mt][nt][3] + bv1 + C[(size_t)(r0 + 8) * 128 + c0 + 1];
                acc[mt][nt][0] = v00; acc[mt][nt][1] = v01;
                acc[mt][nt][2] = v10; acc[mt][nt][3] = v11;
                sums[mt][0] += v00 + v01; sqs[mt][0] += v00 * v00 + v01 * v01;
                sums[mt][1] += v10 + v11; sqs[mt][1] += v10 * v10 + v11 * v11;
            }
        }
        #pragma unroll
        for (int mt = 0; mt < 2; mt++)
            #pragma unroll
            for (int rp = 0; rp < 2; rp++) {
                float s = sums[mt][rp], q = sqs[mt][rp];
                s += __shfl_xor_sync(0xffffffffu, s, 1); q += __shfl_xor_sync(0xffffffffu, q, 1);
                s += __shfl_xor_sync(0xffffffffu, s, 2); q += __shfl_xor_sync(0xffffffffu, q, 2);
                sums[mt][rp] = s; sqs[mt][rp] = q;
            }
        __syncthreads();
        float* red = (float*)As;
        if (tig == 0) {
            #pragma unroll
            for (int mt = 0; mt < 2; mt++)
                #pragma unroll
                for (int rp = 0; rp < 2; rp++) {
                    int ix = ((warp * 16 + g) * 4 + mt * 2 + rp) * 2;
                    red[ix] = sums[mt][rp]; red[ix + 1] = sqs[mt][rp];
                }
        }
        __syncthreads();
        float mean[2][2], inv[2][2];
        #pragma unroll
        for (int mt = 0; mt < 2; mt++)
            #pragma unroll
            for (int rp = 0; rp < 2; rp++) {
                int i0 = (((wm) * 16 + g) * 4 + mt * 2 + rp) * 2;
                int i1 = (((wm + 4) * 16 + g) * 4 + mt * 2 + rp) * 2;
                float s = red[i0] + red[i1];
                float q = red[i0 + 1] + red[i1 + 1];
                float m = s * (1.f / 128.f);
                float var = q * (1.f / 128.f) - m * m;
                mean[mt][rp] = m;
                inv[mt][rp] = rsqrtf(var + 1e-5f);
            }
        #pragma unroll
        for (int mt = 0; mt < 2; mt++) {
            int r0 = bm + wm * 32 + mt * 16 + g;
            #pragma unroll
            for (int nt = 0; nt < 8; nt++) {
                int c0 = wn * 64 + nt * 8 + 2 * tig;
                float g0 = gamma[c0], g1 = gamma[c0 + 1];
                float be0 = beta[c0], be1 = beta[c0 + 1];
                float v00 = (acc[mt][nt][0] - mean[mt][0]) * inv[mt][0] * g0 + be0;
                float v01 = (acc[mt][nt][1] - mean[mt][0]) * inv[mt][0] * g1 + be1;
                float v10 = (acc[mt][nt][2] - mean[mt][1]) * inv[mt][1] * g0 + be0;
                float v11 = (acc[mt][nt][3] - mean[mt][1]) * inv[mt][1] * g1 + be1;
                *(float2*)(C + (size_t)r0 * 128 + c0)       = make_float2(v00, v01);
                *(float2*)(C + (size_t)(r0 + 8) * 128 + c0) = make_float2(v10, v11);
                *(__half2*)(Ch + (size_t)r0 * 128 + c0)       = __floats2half2_rn(v00, v01);
                *(__half2*)(Ch + (size_t)(r0 + 8) * 128 + c0) = __floats2half2_rn(v10, v11);
            }
        }
    } else if (EPI == 3) {
        #pragma unroll
        for (int mt = 0; mt < 2; mt++) {
            int r0 = bm + wm * 32 + mt * 16 + g;
            #pragma unroll
            for (int nt = 0; nt < 8; nt++) {
                int c0 = bn + wn * 64 + nt * 8 + 2 * tig;
                atomicAdd(C + (size_t)r0 * N + c0,           acc[mt][nt][0]);
                atomicAdd(C + (size_t)r0 * N + c0 + 1,       acc[mt][nt][1]);
                atomicAdd(C + (size_t)(r0 + 8) * N + c0,     acc[mt][nt][2]);
                atomicAdd(C + (size_t)(r0 + 8) * N + c0 + 1, acc[mt][nt][3]);
            }
        }
    } else { // EPI == 4: bias + relu -> half
        #pragma unroll
        for (int mt = 0; mt < 2; mt++) {
            int r0 = bm + wm * 32 + mt * 16 + g;
            #pragma unroll
            for (int nt = 0; nt < 8; nt++) {
                int c0 = bn + wn * 64 + nt * 8 + 2 * tig;
                float bv0 = bias[c0], bv1 = bias[c0 + 1];
                float v00 = fmaxf(acc[mt][nt][0] + bv0, 0.f);
                float v01 = fmaxf(acc[mt][nt][1] + bv1, 0.f);
                float v10 = fmaxf(acc[mt][nt][2] + bv0, 0.f);
                float v11 = fmaxf(acc[mt][nt][3] + bv1, 0.f);
                *(__half2*)(Ch + (size_t)r0 * N + c0)       = __floats2half2_rn(v00, v01);
                *(__half2*)(Ch + (size_t)(r0 + 8) * N + c0) = __floats2half2_rn(v10, v11);
            }
        }
    }
}

// ---------------- reparameterization + KLD ----------------
__global__ void k_z(const float* __restrict__ eps, const int* __restrict__ iftrain) {
    int idx = blockIdx.x * 256 + threadIdx.x;
    int i = idx >> 7, j = idx & 127;
    float m = g_MULS[(size_t)i * 256 + j];
    float ls = fminf(g_MULS[(size_t)i * 256 + 128 + j], 10.f);
    float zz = (*iftrain > 0) ? (m + eps[idx] * expf(ls)) : m;
    g_Z[idx] = zz;
    g_ZH[idx] = __float2half(zz);
    float term = 1.f + 2.f * ls - m * m - expf(2.f * ls);
    float bs = block_sum<8>(term);
    if (threadIdx.x == 0) atomicAdd(&g_kld, (double)bs);
}

// ---------------- struct loss: 64x64 tile, 2x2 per thread ----------------
__global__ __launch_bounds__(1024) void k_struct() {
    __shared__ float Zi[64][65];
    __shared__ float Zj[64][65];
    int i0 = blockIdx.y * 64, j0 = blockIdx.x * 64;
    int tid = threadIdx.y * 32 + threadIdx.x;
    int ty = threadIdx.y, tx = threadIdx.x;
    float acc[2][2] = {};
    for (int kc = 0; kc < 128; kc += 64) {
        __syncthreads();
        for (int idx = tid; idx < 64 * 64; idx += 1024) {
            int r = idx >> 6, c = idx & 63;
            Zi[r][c] = g_Z[(size_t)(i0 + r) * H + kc + c];
            Zj[r][c] = g_Z[(size_t)(j0 + r) * H + kc + c];
        }
        __syncthreads();
        #pragma unroll 8
        for (int k = 0; k < 64; k++) {
            float zi0 = Zi[ty * 2][k], zi1 = Zi[ty * 2 + 1][k];
            float zj0 = Zj[tx * 2][k], zj1 = Zj[tx * 2 + 1][k];
            acc[0][0] += zi0 * zj0; acc[0][1] += zi0 * zj1;
            acc[1][0] += zi1 * zj0; acc[1][1] += zi1 * zj1;
        }
    }
    float contrib = 0.f;
    #pragma unroll
    for (int ii = 0; ii < 2; ii++)
        #pragma unroll
        for (int jj = 0; jj < 2; jj++) {
            int i = i0 + ty * 2 + ii, j = j0 + tx * 2 + jj;
            float a = acc[ii][jj];
            float adj = g_ADJ[(size_t)i * NNODE + j];
            contrib += fmaxf(a, 0.f) - a * adj + log1pf(expf(-fabsf(a)));
        }
    float bs = block_sum<32>(contrib);
    if (tid == 0) atomicAdd(&g_struct, (double)bs);
}

// ---------------- build transformer input x ----------------
__global__ void k_xbuild(const float* __restrict__ w3, const float* __restrict__ b3) {
    int idx = blockIdx.x * 256 + threadIdx.x;
    int j = idx & 127;
    int tok = idx >> 7;
    int a = tok >> 7, h = tok & 127;
    float acc = b3[j];
    #pragma unroll
    for (int t = 0; t < OBS; t++)
        acc += g_OUTB[(size_t)((t << 8) + a) * H + h] * w3[j * OBS + t];
    g_X[idx] = acc;
    g_XH[idx] = __float2half(acc);
}

// ---------------- attention: half QKV in [p][h][b][s][d]; half O out --------
__global__ __launch_bounds__(128) void k_attn() {
    __shared__ __half2 Ks[256 * 8];
    __shared__ __half2 Vs[256 * 8];
    int bh = blockIdx.x;
    int b = bh >> 3, h = bh & 7;
    int t = threadIdx.x;
    const __half* Qb = g_QKVH + ((size_t)((0 * 8 + h) * 128 + b)) * 4096;
    const __half* Kb = g_QKVH + ((size_t)((1 * 8 + h) * 128 + b)) * 4096;
    const __half* Vb = g_QKVH + ((size_t)((2 * 8 + h) * 128 + b)) * 4096;
    for (int i = t; i < 512; i += 128) {
        ((uint4*)Ks)[i] = ((const uint4*)Kb)[i];
        ((uint4*)Vs)[i] = ((const uint4*)Vb)[i];
    }
    __syncthreads();
    float q[2][16], o[2][16] = {};
    float m[2], l[2];
    #pragma unroll
    for (int rr = 0; rr < 2; rr++) {
        int s = t + rr * 128;
        const __half2* qp = (const __half2*)(Qb + (size_t)s * 16);
        #pragma unroll
        for (int j = 0; j < 8; j++) {
            float2 f = __half22float2(qp[j]);
            q[rr][2 * j] = f.x; q[rr][2 * j + 1] = f.y;
        }
        m[rr] = __int_as_float(0xff800000);
        l[rr] = 0.f;
    }
    for (int tt = 0; tt < 256; tt++) {
        float kr[16], vr[16];
        #pragma unroll
        for (int j = 0; j < 8; j++) {
            float2 kf = __half22float2(Ks[tt * 8 + j]);
            kr[2 * j] = kf.x; kr[2 * j + 1] = kf.y;
            float2 vf = __half22float2(Vs[tt * 8 + j]);
            vr[2 * j] = vf.x; vr[2 * j + 1] = vf.y;
        }
        #pragma unroll
        for (int rr = 0; rr < 2; rr++) {
            float sc = 0.f;
            #pragma unroll
            for (int d = 0; d < 16; d++) sc += q[rr][d] * kr[d];
            sc *= 0.25f;
            float mn = fmaxf(m[rr], sc);
            float corr = __expf(m[rr] - mn);
            float p = __expf(sc - mn);
            l[rr] = l[rr] * corr + p;
            #pragma unroll
            for (int d = 0; d < 16; d++) o[rr][d] = o[rr][d] * corr + p * vr[d];
            m[rr] = mn;
        }
    }
    #pragma unroll
    for (int rr = 0; rr < 2; rr++) {
        int s = t + rr * 128;
        float invl = 1.f / l[rr];
        __half2* op = (__half2*)(g_OH + ((size_t)s * BB + b) * H + h * DH);
        #pragma unroll
        for (int j = 0; j < 8; j++)
            op[j] = __floats2half2_rn(o[rr][2 * j] * invl, o[rr][2 * j + 1] * invl);
    }
}

// ---------------- final projection + traj output + traj loss ----------------
__global__ void k_traj(const float* __restrict__ w4, const float* __restrict__ b4,
                       const float* __restrict__ w5, const float* __restrict__ b5,
                       const float* __restrict__ traj_in, float* __restrict__ out) {
    int tt = blockIdx.x >> 8;
    int a  = blockIdx.x & 255;
    int b  = threadIdx.x;
    int o = tt + (OBS - PRED);
    const float* xr = g_X + ((size_t)a * 128 + b) * 128;
    float acc = b4[o];
    #pragma unroll 8
    for (int j = 0; j < 128; j++) acc += xr[j] * w4[o * 128 + j];
    float s0 = block_sum<4>(acc * w5[b]);
    float s1 = block_sum<4>(acc * w5[128 + b]);
    if (b == 0) {
        float t0 = s0 + b5[0], t1 = s1 + b5[1];
        float y0 = traj_in[(OBS + tt) * (NAG * 2) + a * 2 + 0];
        float y1 = traj_in[(OBS + tt) * (NAG * 2) + a * 2 + 1];
        out[(tt * 256 + a) * 2 + 0] = t0;
        out[(tt * 256 + a) * 2 + 1] = t1;
        float d0 = t0 - y0, d1 = t1 - y1;
        atomicAdd(&g_traj, (double)sqrtf(d0 * d0 + d1 * d1));
    }
}

__global__ void k_final(float* __restrict__ out) {
    double kld = -0.5 * (g_kld / 2048.0);
    double st = g_struct / (2048.0 * 2048.0);
    double tl = g_traj / 256.0;
    out[PRED * NAG * FOUT] = (float)(tl + kld + st);
}

// ---------------- launch ----------------
extern "C" void kernel_launch(void* const* d_in, const int* in_sizes, int n_in,
                              void* d_out, int out_size) {
    const float* traj_in = (const float*)d_in[0];
    const float* adj_in  = (const float*)d_in[1];
    const float* eps     = (const float*)d_in[2];
    const float* pro1_w  = (const float*)d_in[3];
    const float* pro1_b  = (const float*)d_in[4];
    const float* pro2_w  = (const float*)d_in[5];
    const float* pro2_b  = (const float*)d_in[6];
    const float* mu_w    = (const float*)d_in[7];
    const float* mu_b    = (const float*)d_in[8];
    const float* ls_w    = (const float*)d_in[9];
    const float* ls_b    = (const float*)d_in[10];
    const float* gdl_w   = (const float*)d_in[11];
    const float* gdl_b   = (const float*)d_in[12];
    const float* pro3_w  = (const float*)d_in[13];
    const float* pro3_b  = (const float*)d_in[14];
    const float* pro4_w  = (const float*)d_in[15];
    const float* pro4_b  = (const float*)d_in[16];
    const float* pro5_w  = (const float*)d_in[17];
    const float* pro5_b  = (const float*)d_in[18];
    const float* qkv_w   = (const float*)d_in[19];
    const float* qkv_b   = (const float*)d_in[20];
    const float* out_w   = (const float*)d_in[21];
    const float* out_b   = (const float*)d_in[22];
    const float* ff1_w   = (const float*)d_in[23];
    const float* ff1_b   = (const float*)d_in[24];
    const float* ff2_w   = (const float*)d_in[25];
    const float* ff2_b   = (const float*)d_in[26];
    const float* ln1_g   = (const float*)d_in[27];
    const float* ln1_b   = (const float*)d_in[28];
    const float* ln2_g   = (const float*)d_in[29];
    const float* ln2_b   = (const float*)d_in[30];
    const int*   iftrain = (const int*)d_in[31];
    float* out = (float*)d_out;

    float *pENC, *pMULS, *pZ, *pOUTB, *pX;
    __half *pMLSH, *pAGGH, *pZH, *pXH, *pOH, *pQKVH, *pFFHH;
    __half *pWQKVH, *pWOUTH, *pWFF1H, *pWFF2H, *pWGDLH;
    cudaGetSymbolAddress((void**)&pENC,   g_ENC);
    cudaGetSymbolAddress((void**)&pMULS,  g_MULS);
    cudaGetSymbolAddress((void**)&pZ,     g_Z);
    cudaGetSymbolAddress((void**)&pOUTB,  g_OUTB);
    cudaGetSymbolAddress((void**)&pX,     g_X);
    cudaGetSymbolAddress((void**)&pMLSH,  g_MLSH);
    cudaGetSymbolAddress((void**)&pAGGH,  g_AGGH);
    cudaGetSymbolAddress((void**)&pZH,    g_ZH);
    cudaGetSymbolAddress((void**)&pXH,    g_XH);
    cudaGetSymbolAddress((void**)&pOH,    g_OH);
    cudaGetSymbolAddress((void**)&pQKVH,  g_QKVH);
    cudaGetSymbolAddress((void**)&pFFHH,  g_FFHH);
    cudaGetSymbolAddress((void**)&pWQKVH, g_WQKVH);
    cudaGetSymbolAddress((void**)&pWOUTH, g_WOUTH);
    cudaGetSymbolAddress((void**)&pWFF1H, g_WFF1H);
    cudaGetSymbolAddress((void**)&pWFF2H, g_WFF2H);
    cudaGetSymbolAddress((void**)&pWGDLH, g_WGDLH);

    // ---- weight conversions (once per replay) ----
    k_f2h<<<(NL*3*H*H + 255)/256, 256>>>(qkv_w, pWQKVH, NL*3*H*H);
    k_f2h<<<(NL*H*H + 255)/256, 256>>>(out_w, pWOUTH, NL*H*H);
    k_f2h<<<(NL*FFD*H + 255)/256, 256>>>(ff1_w, pWFF1H, NL*FFD*H);
    k_f2h<<<(NL*FFD*H + 255)/256, 256>>>(ff2_w, pWFF2H, NL*FFD*H);
    k_f2h<<<(H*H + 255)/256, 256>>>(gdl_w, pWGDLH, H*H);

    // ---- graph-VAE front end ----
    k_init<<<8, 256>>>();
    k_zero<<<(NNODE * 256 + 255) / 256, 256>>>(pMULS, NNODE * 256);
    k_minmax<<<512, 256>>>(adj_in);
    k_build<<<dim3(8, NNODE), 256>>>(adj_in);
    k_colsum<<<dim3(16, 64), 128>>>();
    k_dis<<<8, 256>>>();
    k_agg<<<dim3(64, 64), dim3(32, 32)>>>();
    k_enc<<<NNODE, 128>>>(traj_in, pro1_w, pro1_b, pro2_w, pro2_b);

    // mu_lin^T / ls_lin^T packed into [256][2048] half buffer
    k_gemm<<<dim3(2, 32), 256>>>(pENC, mu_w, mu_b, pMLSH, NNODE, H, H);
    k_gemm<<<dim3(2, 32), 256>>>(pENC, ls_w, ls_b, pMLSH + (size_t)128 * NNODE, NNODE, H, H);
    // [MU | LSR] = AGG @ [mu_lin | ls_lin]  (split-K fp16 GEMM)
    k_hgemm<3><<<dim3(2, 16, 8), 256>>>(pAGGH, pMLSH, nullptr, pMULS, nullptr,
                                        NNODE, 256, NNODE, 0, nullptr, nullptr);
    k_z<<<1024, 256>>>(eps, iftrain);
    k_struct<<<dim3(32, 32), dim3(32, 32)>>>();
    k_hgemm<0><<<dim3(1, 16), 256>>>(pZH, pWGDLH, gdl_b, pOUTB, nullptr,
                                     NNODE, H, H, 0, nullptr, nullptr);
    k_xbuild<<<16384, 256>>>(pro3_w, pro3_b);

    // ---- transformer ----
    for (int l = 0; l < NL; l++) {
        k_hgemm<1><<<dim3(3, 256), 256>>>(pXH, pWQKVH + (size_t)l * 3 * H * H, qkv_b + (size_t)l * 3 * H,
                                          nullptr, pQKVH, NTOK, 3 * H, H, 0, nullptr, nullptr);
        k_attn<<<BB * NH, 128>>>();
        k_hgemm<2><<<dim3(1, 256), 256>>>(pOH, pWOUTH + (size_t)l * H * H, out_b + (size_t)l * H,
                                          pX, pXH, NTOK, H, H, 0, ln1_g + l * H, ln1_b + l * H);
        k_hgemm<4><<<dim3(16, 256), 256>>>(pXH, pWFF1H + (size_t)l * FFD * H, ff1_b + (size_t)l * FFD,
                                           nullptr, pFFHH, NTOK, FFD, H, 1, nullptr, nullptr);
        k_hgemm<2><<<dim3(1, 256), 256>>>(pFFHH, pWFF2H + (size_t)l * H * FFD, ff2_b + (size_t)l * H,
                                          pX, pXH, NTOK, H, FFD, 0, ln2_g + l * H, ln2_b + l * H);
    }

    // ---- output + loss ----
    k_traj<<<PRED * NAG, 128>>>(pro4_w, pro4_b, pro5_w, pro5_b, traj_in, out);
    k_final<<<1, 1>>>(out);
}